// round 6
// baseline (speedup 1.0000x reference)
#include <cuda_runtime.h>
#include <math.h>
#include <stdint.h>

// ---------------- problem constants ----------------
#define HH 56
#define WW_ 56
#define CC 512
#define NHEAD 16
#define WSZ 7
#define SSH 3
#define HID 2048
#define HD 32
#define NTOK 49           // tokens per window
#define NWH 8
#define NWW 8
#define NWIN 64
#define BB 16
#define TOT (BB*HH*WW_)   // 50176 tokens
#define LN_EPS 1e-5f
#define ATT_SCALE 0.17677669529663687f  // 32^-0.5

// ---------------- scratch (device globals, no allocs) ----------------
__device__ float g_h   [TOT * CC];        // LN1+windowed  (reused as h2)
__device__ float g_qkv [TOT * 3 * CC];    // qkv
__device__ float g_o   [TOT * CC];        // attention out (window layout)
__device__ float g_act [TOT * HID];       // fc1 activations

// ---------------- LayerNorm (optionally fused shift+window gather) ----------------
template<bool GATHER>
__global__ void ln_kernel(const float* __restrict__ src,
                          const float* __restrict__ scale,
                          const float* __restrict__ bias,
                          float* __restrict__ dst)
{
    int t = blockIdx.x;
    const float* sp;
    if (GATHER) {
        int b   = t / (NWIN * NTOK);
        int rem = t % (NWIN * NTOK);
        int win = rem / NTOK, pos = rem % NTOK;
        int wh = win / NWW, ww = win % NWW;
        int p = pos / WSZ, q = pos % WSZ;
        int row = (wh * WSZ + p + SSH) % HH;     // roll(-3)
        int col = (ww * WSZ + q + SSH) % WW_;
        sp = src + ((size_t)(b * HH + row) * WW_ + col) * CC;
    } else {
        sp = src + (size_t)t * CC;
    }
    float* dp = dst + (size_t)t * CC;

    int tid = threadIdx.x;                 // 128 threads, 4 floats each
    float4 v = *(const float4*)(sp + tid * 4);
    float s  = v.x + v.y + v.z + v.w;
    float s2 = v.x*v.x + v.y*v.y + v.z*v.z + v.w*v.w;

    __shared__ float red[8];
    #pragma unroll
    for (int off = 16; off > 0; off >>= 1) {
        s  += __shfl_down_sync(0xffffffffu, s,  off);
        s2 += __shfl_down_sync(0xffffffffu, s2, off);
    }
    int wid = tid >> 5, lane = tid & 31;
    if (lane == 0) { red[wid] = s; red[4 + wid] = s2; }
    __syncthreads();
    if (tid == 0) {
        float S  = red[0] + red[1] + red[2] + red[3];
        float S2 = red[4] + red[5] + red[6] + red[7];
        float mu  = S * (1.0f / CC);
        float var = S2 * (1.0f / CC) - mu * mu;
        red[0] = mu;
        red[1] = rsqrtf(var + LN_EPS);
    }
    __syncthreads();
    float mu = red[0], rs = red[1];
    float4 sc = *(const float4*)(scale + tid * 4);
    float4 bi = *(const float4*)(bias  + tid * 4);
    float4 o;
    o.x = (v.x - mu) * rs * sc.x + bi.x;
    o.y = (v.y - mu) * rs * sc.y + bi.y;
    o.z = (v.z - mu) * rs * sc.z + bi.z;
    o.w = (v.w - mu) * rs * sc.w + bi.w;
    *(float4*)(dp + tid * 4) = o;
}

// ---------------- TF32 tensor-core GEMM, 128x128 block, 4 warps, 64x64 warp tile ----------------
__device__ __forceinline__ float gelu_exact(float x) {
    return 0.5f * x * (1.0f + erff(x * 0.70710678118654752f));
}
__device__ __forceinline__ void cp_async16(uint32_t dst, const void* src) {
    asm volatile("cp.async.cg.shared.global [%0], [%1], 16;" :: "r"(dst), "l"(src));
}

#define ASTR 36                // A smem row stride (floats), conflict-free frag loads
#define BSTR 136               // B smem row stride (floats)
#define KST 32                 // k per stage
#define A_STG (128 * ASTR)     // floats per A stage
#define B_STG (KST * BSTR)     // floats per B stage
#define TG_SMEM ((2 * A_STG + 2 * B_STG) * 4)   // 71680 bytes

// EPI: 0=bias, 1=bias+GELU, 2=bias+residual, 3=bias+window-reverse-scatter+residual
template<int EPI>
__global__ __launch_bounds__(128, 2)
void tgemm_kernel(const float* __restrict__ A, const float* __restrict__ B,
                  const float* __restrict__ bias, float* __restrict__ Cout,
                  const float* __restrict__ res, int M, int N, int K)
{
    extern __shared__ float sh[];
    float* As = sh;                       // [2][128][ASTR]
    float* Bs = sh + 2 * A_STG;           // [2][KST][BSTR]

    const int bx = blockIdx.x;            // N tile (128)
    const int by = blockIdx.y;            // M tile (128)
    const int tid = threadIdx.x;          // 128
    const int wid = tid >> 5, lane = tid & 31;
    const int wm = wid & 1;               // 2 warps in M (64 rows each)
    const int wn = wid >> 1;              // 2 warps in N (64 cols each)
    const int lr = lane >> 2;             // 0..7
    const int lc = lane & 3;              // 0..3

    float acc[4][8][4];
    #pragma unroll
    for (int i = 0; i < 4; i++)
        #pragma unroll
        for (int j = 0; j < 8; j++) {
            acc[i][j][0] = 0.f; acc[i][j][1] = 0.f;
            acc[i][j][2] = 0.f; acc[i][j][3] = 0.f;
        }

    // A staging via cp.async: thread -> row tid, 8 x 16B chunks (full KST cols)
    const float* Ag = A + (size_t)(by * 128 + tid) * K;
    // B staging via cp.async: thread -> row tid>>2 (0..31), 8 x 16B chunks
    const int b_row = tid >> 2;
    const int b_c0  = (tid & 3) * 4;
    const float* Bg = B + (size_t)b_row * N + bx * 128 + b_c0;

    const int NS = K / KST;

    // ---- prologue: stage 0 ----
    {
        uint32_t ad = (uint32_t)__cvta_generic_to_shared(As + tid * ASTR);
        #pragma unroll
        for (int c = 0; c < 8; c++) cp_async16(ad + c * 16, Ag + c * 4);
        uint32_t bd = (uint32_t)__cvta_generic_to_shared(Bs + b_row * BSTR + b_c0);
        #pragma unroll
        for (int c = 0; c < 8; c++) cp_async16(bd + c * 64, Bg + c * 16);
        asm volatile("cp.async.commit_group;");
        asm volatile("cp.async.wait_group 0;");
    }
    __syncthreads();

    for (int s = 0; s < NS; s++) {
        if (s + 1 < NS) {
            const float* Agn = Ag + (s + 1) * KST;
            uint32_t ad = (uint32_t)__cvta_generic_to_shared(
                As + ((s + 1) & 1) * A_STG + tid * ASTR);
            #pragma unroll
            for (int c = 0; c < 8; c++) cp_async16(ad + c * 16, Agn + c * 4);
            const float* Bgn = Bg + (size_t)(s + 1) * KST * N;
            uint32_t bd = (uint32_t)__cvta_generic_to_shared(
                Bs + ((s + 1) & 1) * B_STG + b_row * BSTR + b_c0);
            #pragma unroll
            for (int c = 0; c < 8; c++) cp_async16(bd + c * 64, Bgn + c * 16);
            asm volatile("cp.async.commit_group;");
        }

        const float* Ab = As + (s & 1) * A_STG;
        const float* Bb = Bs + (s & 1) * B_STG;

        uint32_t af[2][4][4], bf[2][8][2];

        // load fragments for kk=0
        #pragma unroll
        for (int mi = 0; mi < 4; mi++) {
            int m = wm * 64 + mi * 16 + lr;
            af[0][mi][0] = __float_as_uint(Ab[(size_t)m * ASTR + lc]);
            af[0][mi][1] = __float_as_uint(Ab[(size_t)(m + 8) * ASTR + lc]);
            af[0][mi][2] = __float_as_uint(Ab[(size_t)m * ASTR + lc + 4]);
            af[0][mi][3] = __float_as_uint(Ab[(size_t)(m + 8) * ASTR + lc + 4]);
        }
        #pragma unroll
        for (int ni = 0; ni < 8; ni++) {
            int n = wn * 64 + ni * 8 + lr;
            bf[0][ni][0] = __float_as_uint(Bb[(size_t)lc * BSTR + n]);
            bf[0][ni][1] = __float_as_uint(Bb[(size_t)(lc + 4) * BSTR + n]);
        }

        #pragma unroll
        for (int kk = 0; kk < KST; kk += 8) {
            const int cur = (kk >> 3) & 1;
            const int nxt = cur ^ 1;
            if (kk + 8 < KST) {
                #pragma unroll
                for (int mi = 0; mi < 4; mi++) {
                    int m = wm * 64 + mi * 16 + lr;
                    af[nxt][mi][0] = __float_as_uint(Ab[(size_t)m * ASTR + kk + 8 + lc]);
                    af[nxt][mi][1] = __float_as_uint(Ab[(size_t)(m + 8) * ASTR + kk + 8 + lc]);
                    af[nxt][mi][2] = __float_as_uint(Ab[(size_t)m * ASTR + kk + 8 + lc + 4]);
                    af[nxt][mi][3] = __float_as_uint(Ab[(size_t)(m + 8) * ASTR + kk + 8 + lc + 4]);
                }
                #pragma unroll
                for (int ni = 0; ni < 8; ni++) {
                    int n = wn * 64 + ni * 8 + lr;
                    bf[nxt][ni][0] = __float_as_uint(Bb[(size_t)(kk + 8 + lc) * BSTR + n]);
                    bf[nxt][ni][1] = __float_as_uint(Bb[(size_t)(kk + 8 + lc + 4) * BSTR + n]);
                }
            }
            #pragma unroll
            for (int mi = 0; mi < 4; mi++)
                #pragma unroll
                for (int ni = 0; ni < 8; ni++) {
                    asm volatile(
                        "mma.sync.aligned.m16n8k8.row.col.f32.tf32.tf32.f32 "
                        "{%0,%1,%2,%3}, {%4,%5,%6,%7}, {%8,%9}, {%0,%1,%2,%3};"
                        : "+f"(acc[mi][ni][0]), "+f"(acc[mi][ni][1]),
                          "+f"(acc[mi][ni][2]), "+f"(acc[mi][ni][3])
                        : "r"(af[cur][mi][0]), "r"(af[cur][mi][1]),
                          "r"(af[cur][mi][2]), "r"(af[cur][mi][3]),
                          "r"(bf[cur][ni][0]), "r"(bf[cur][ni][1]));
                }
        }

        if (s + 1 < NS) asm volatile("cp.async.wait_group 0;");
        __syncthreads();
    }

    // ---------------- epilogue ----------------
    const int m_base = by * 128 + wm * 64;
    const int n_base = bx * 128 + wn * 64;

    float2 bv[8];
    #pragma unroll
    for (int ni = 0; ni < 8; ni++)
        bv[ni] = *(const float2*)(bias + n_base + ni * 8 + 2 * lc);

    #pragma unroll
    for (int mi = 0; mi < 4; mi++) {
        int r0 = m_base + mi * 16 + lr;
        int r1 = r0 + 8;
        size_t orow0 = (size_t)r0, orow1 = (size_t)r1;
        if (EPI == 3) {
            // window layout row -> spatial row (reverse shift + window reverse)
            int rows[2] = {r0, r1};
            size_t mapped[2];
            #pragma unroll
            for (int u = 0; u < 2; u++) {
                int t = rows[u];
                int b   = t / (NWIN * NTOK);
                int rem = t % (NWIN * NTOK);
                int win = rem / NTOK, pos = rem % NTOK;
                int wh = win >> 3, ww = win & 7;
                int p = pos / WSZ, q = pos % WSZ;
                int r = wh * WSZ + p + SSH; if (r >= HH) r -= HH;
                int c = ww * WSZ + q + SSH; if (c >= WW_) c -= WW_;
                mapped[u] = (size_t)(b * HH + r) * WW_ + c;
            }
            orow0 = mapped[0]; orow1 = mapped[1];
        }
        #pragma unroll
        for (int ni = 0; ni < 8; ni++) {
            int col = n_base + ni * 8 + 2 * lc;
            size_t off0 = orow0 * N + col;
            size_t off1 = orow1 * N + col;
            float2 v0, v1;
            v0.x = acc[mi][ni][0] + bv[ni].x;
            v0.y = acc[mi][ni][1] + bv[ni].y;
            v1.x = acc[mi][ni][2] + bv[ni].x;
            v1.y = acc[mi][ni][3] + bv[ni].y;
            if (EPI == 1) {
                v0.x = gelu_exact(v0.x); v0.y = gelu_exact(v0.y);
                v1.x = gelu_exact(v1.x); v1.y = gelu_exact(v1.y);
            }
            if (EPI == 2 || EPI == 3) {
                float2 q0 = *(const float2*)(res + off0);
                float2 q1 = *(const float2*)(res + off1);
                v0.x += q0.x; v0.y += q0.y;
                v1.x += q1.x; v1.y += q1.y;
            }
            *(float2*)(Cout + off0) = v0;
            *(float2*)(Cout + off1) = v1;
        }
    }
}

// ---------------- windowed attention: one block per (window, head) ----------------
__global__ void attn_kernel(const float* __restrict__ qkv,
                            const float* __restrict__ rpb_table,
                            float* __restrict__ o)
{
    int head = blockIdx.x;
    int win  = blockIdx.y;             // b*NWIN + w
    int wloc = win % NWIN;
    int wh = wloc / NWW, ww = wloc % NWW;

    __shared__ float Qs[NTOK][33];
    __shared__ float Ks[NTOK][33];
    __shared__ float Vs[NTOK][33];
    __shared__ float Ss[NTOK][NTOK];
    __shared__ float rpbs[169];
    __shared__ int   regn[NTOK];

    int tid = threadIdx.x;             // 128

    const float* base = qkv + (size_t)win * NTOK * (3 * CC) + head * HD;
    for (int i = tid; i < NTOK * 8; i += 128) {
        int n = i >> 3, d4 = (i & 7) * 4;
        const float* rp = base + (size_t)n * (3 * CC);
        float4 q4 = *(const float4*)(rp + d4);
        float4 k4 = *(const float4*)(rp + CC + d4);
        float4 v4 = *(const float4*)(rp + 2 * CC + d4);
        Qs[n][d4] = q4.x; Qs[n][d4+1] = q4.y; Qs[n][d4+2] = q4.z; Qs[n][d4+3] = q4.w;
        Ks[n][d4] = k4.x; Ks[n][d4+1] = k4.y; Ks[n][d4+2] = k4.z; Ks[n][d4+3] = k4.w;
        Vs[n][d4] = v4.x; Vs[n][d4+1] = v4.y; Vs[n][d4+2] = v4.z; Vs[n][d4+3] = v4.w;
    }
    for (int i = tid; i < 169; i += 128) rpbs[i] = rpb_table[i * NHEAD + head];
    if (tid < NTOK) {
        int p = tid / WSZ, q = tid % WSZ;
        int r = wh * WSZ + p, c = ww * WSZ + q;       // shifted-frame coords
        int rr = (r < 49) ? 0 : ((r < 53) ? 1 : 2);
        int rc = (c < 49) ? 0 : ((c < 53) ? 1 : 2);
        regn[tid] = rr * 3 + rc;
    }
    __syncthreads();

    // scores + rpb + mask
    for (int i = tid; i < NTOK * NTOK; i += 128) {
        int n = i / NTOK, m = i % NTOK;
        float acc = 0.0f;
        #pragma unroll
        for (int d = 0; d < HD; d++) acc += Qs[n][d] * Ks[m][d];
        int in_ = n / WSZ, jn = n % WSZ;
        int im  = m / WSZ, jm = m % WSZ;
        int ridx = (jn - jm + 6) * 13 + (in_ - im + 6);
        float val = acc * ATT_SCALE + rpbs[ridx];
        if (regn[n] != regn[m]) val -= 100.0f;
        Ss[n][m] = val;
    }
    __syncthreads();

    // row softmax (thread r owns row r)
    if (tid < NTOK) {
        float mx = -1e30f;
        #pragma unroll 7
        for (int m = 0; m < NTOK; m++) mx = fmaxf(mx, Ss[tid][m]);
        float sum = 0.0f;
        #pragma unroll 7
        for (int m = 0; m < NTOK; m++) {
            float e = expf(Ss[tid][m] - mx);
            Ss[tid][m] = e;
            sum += e;
        }
        float inv = 1.0f / sum;
        #pragma unroll 7
        for (int m = 0; m < NTOK; m++) Ss[tid][m] *= inv;
    }
    __syncthreads();

    // O = P @ V
    float* obase = o + (size_t)win * NTOK * CC + head * HD;
    for (int i = tid; i < NTOK * HD; i += 128) {
        int n = i >> 5, d = i & 31;
        float acc = 0.0f;
        #pragma unroll 7
        for (int m = 0; m < NTOK; m++) acc += Ss[n][m] * Vs[m][d];
        obase[(size_t)n * CC + d] = acc;
    }
}

// ---------------- host launcher ----------------
extern "C" void kernel_launch(void* const* d_in, const int* in_sizes, int n_in,
                              void* d_out, int out_size)
{
    const float* x      = (const float*)d_in[0];
    const float* ln1_s  = (const float*)d_in[1];
    const float* ln1_b  = (const float*)d_in[2];
    const float* qkv_w  = (const float*)d_in[3];
    const float* qkv_b  = (const float*)d_in[4];
    const float* rpb    = (const float*)d_in[5];
    const float* proj_w = (const float*)d_in[6];
    const float* proj_b = (const float*)d_in[7];
    const float* ln2_s  = (const float*)d_in[8];
    const float* ln2_b  = (const float*)d_in[9];
    const float* fc1_w  = (const float*)d_in[10];
    const float* fc1_b  = (const float*)d_in[11];
    const float* fc2_w  = (const float*)d_in[12];
    const float* fc2_b  = (const float*)d_in[13];
    float* out = (float*)d_out;

    float *ph, *pqkv, *po, *pact;
    cudaGetSymbolAddress((void**)&ph,   g_h);
    cudaGetSymbolAddress((void**)&pqkv, g_qkv);
    cudaGetSymbolAddress((void**)&po,   g_o);
    cudaGetSymbolAddress((void**)&pact, g_act);

    static int smem_set = 0;
    if (!smem_set) {
        cudaFuncSetAttribute(tgemm_kernel<0>, cudaFuncAttributeMaxDynamicSharedMemorySize, TG_SMEM);
        cudaFuncSetAttribute(tgemm_kernel<1>, cudaFuncAttributeMaxDynamicSharedMemorySize, TG_SMEM);
        cudaFuncSetAttribute(tgemm_kernel<2>, cudaFuncAttributeMaxDynamicSharedMemorySize, TG_SMEM);
        cudaFuncSetAttribute(tgemm_kernel<3>, cudaFuncAttributeMaxDynamicSharedMemorySize, TG_SMEM);
        smem_set = 1;
    }

    // 1. LN1 + shift + window partition
    ln_kernel<true><<<TOT, 128>>>(x, ln1_s, ln1_b, ph);
    // 2. QKV GEMM [50176,512]x[512,1536]
    tgemm_kernel<0><<<dim3(1536/128, TOT/128), 128, TG_SMEM>>>(ph, qkv_w, qkv_b, pqkv, nullptr, TOT, 1536, 512);
    // 3. windowed attention
    attn_kernel<<<dim3(NHEAD, BB * NWIN), 128>>>(pqkv, rpb, po);
    // 4. proj GEMM + fused window-reverse scatter + residual -> out
    tgemm_kernel<3><<<dim3(512/128, TOT/128), 128, TG_SMEM>>>(po, proj_w, proj_b, out, x, TOT, 512, 512);
    // 5. LN2
    ln_kernel<false><<<TOT, 128>>>(out, ln2_s, ln2_b, ph);
    // 6. FC1 + GELU [50176,512]x[512,2048]
    tgemm_kernel<1><<<dim3(HID/128, TOT/128), 128, TG_SMEM>>>(ph, fc1_w, fc1_b, pact, nullptr, TOT, HID, 512);
    // 7. FC2 + residual [50176,2048]x[2048,512]
    tgemm_kernel<2><<<dim3(512/128, TOT/128), 128, TG_SMEM>>>(pact, fc2_w, fc2_b, out, out, TOT, 512, HID);
}

// round 9
// speedup vs baseline: 1.3640x; 1.3640x over previous
#include <cuda_runtime.h>
#include <cuda_fp16.h>
#include <math.h>
#include <stdint.h>

// ---------------- problem constants ----------------
#define HH 56
#define WW_ 56
#define CC 512
#define NHEAD 16
#define WSZ 7
#define SSH 3
#define HID 2048
#define HD 32
#define NTOK 49
#define NWH 8
#define NWW 8
#define NWIN 64
#define BB 16
#define TOT (BB*HH*WW_)   // 50176 tokens
#define LN_EPS 1e-5f
#define ATT_SCALE 0.17677669529663687f

// ---------------- scratch (device globals, no allocs) ----------------
__device__ __align__(16) __half g_h16  [TOT * CC];        // LN outputs (A for qkv/fc1)
__device__ __align__(16) __half g_qkv16[TOT * 3 * CC];    // qkv (fp16)
__device__ __align__(16) __half g_o16  [TOT * CC];        // attention out (A for proj)
__device__ __align__(16) __half g_act16[TOT * HID];       // fc1+gelu activations (A for fc2)
// transposed fp16 weights [N][K]
#define WQKV_OFF 0
#define WPROJ_OFF (512*1536)
#define WFC1_OFF  (WPROJ_OFF + 512*512)
#define WFC2_OFF  (WFC1_OFF + 512*2048)
__device__ __align__(16) __half g_wt[512*1536 + 512*512 + 512*2048 + 2048*512];

// ---------------- weight convert + transpose: W[K][N] f32 -> Wt[N][K] f16 ----------------
__global__ void wconv_kernel(const float* __restrict__ W, __half* __restrict__ Wt,
                             int K, int N)
{
    __shared__ float t[32][33];
    int nx = blockIdx.x * 32, ky = blockIdx.y * 32;
    int tx = threadIdx.x, ty = threadIdx.y;      // 32 x 8
    #pragma unroll
    for (int j = 0; j < 32; j += 8)
        t[ty + j][tx] = W[(size_t)(ky + ty + j) * N + nx + tx];
    __syncthreads();
    #pragma unroll
    for (int j = 0; j < 32; j += 8)
        Wt[(size_t)(nx + ty + j) * K + ky + tx] = __float2half(t[tx][ty + j]);
}

// ---------------- LayerNorm (optionally fused shift+window gather), fp16 out ----------------
template<bool GATHER>
__global__ void ln_kernel(const float* __restrict__ src,
                          const float* __restrict__ scale,
                          const float* __restrict__ bias,
                          __half* __restrict__ dst)
{
    int t = blockIdx.x;
    const float* sp;
    if (GATHER) {
        int b   = t / (NWIN * NTOK);
        int rem = t % (NWIN * NTOK);
        int win = rem / NTOK, pos = rem % NTOK;
        int wh = win / NWW, ww = win % NWW;
        int p = pos / WSZ, q = pos % WSZ;
        int row = (wh * WSZ + p + SSH) % HH;
        int col = (ww * WSZ + q + SSH) % WW_;
        sp = src + ((size_t)(b * HH + row) * WW_ + col) * CC;
    } else {
        sp = src + (size_t)t * CC;
    }
    __half* dp = dst + (size_t)t * CC;

    int tid = threadIdx.x;                 // 128 threads, 4 floats each
    float4 v = *(const float4*)(sp + tid * 4);
    float s  = v.x + v.y + v.z + v.w;
    float s2 = v.x*v.x + v.y*v.y + v.z*v.z + v.w*v.w;

    __shared__ float red[8];
    #pragma unroll
    for (int off = 16; off > 0; off >>= 1) {
        s  += __shfl_down_sync(0xffffffffu, s,  off);
        s2 += __shfl_down_sync(0xffffffffu, s2, off);
    }
    int wid = tid >> 5, lane = tid & 31;
    if (lane == 0) { red[wid] = s; red[4 + wid] = s2; }
    __syncthreads();
    if (tid == 0) {
        float S  = red[0] + red[1] + red[2] + red[3];
        float S2 = red[4] + red[5] + red[6] + red[7];
        float mu  = S * (1.0f / CC);
        float var = S2 * (1.0f / CC) - mu * mu;
        red[0] = mu;
        red[1] = rsqrtf(var + LN_EPS);
    }
    __syncthreads();
    float mu = red[0], rs = red[1];
    float4 sc = *(const float4*)(scale + tid * 4);
    float4 bi = *(const float4*)(bias  + tid * 4);
    float ox = (v.x - mu) * rs * sc.x + bi.x;
    float oy = (v.y - mu) * rs * sc.y + bi.y;
    float oz = (v.z - mu) * rs * sc.z + bi.z;
    float ow = (v.w - mu) * rs * sc.w + bi.w;
    __half2 h0 = __floats2half2_rn(ox, oy);
    __half2 h1 = __floats2half2_rn(oz, ow);
    *(__half2*)(dp + tid * 4)     = h0;
    *(__half2*)(dp + tid * 4 + 2) = h1;
}

// ---------------- fp16 tensor-core GEMM, 128x128 block, 4 warps, 64x64 warp tile ----------------
__device__ __forceinline__ float gelu_exact(float x) {
    return 0.5f * x * (1.0f + erff(x * 0.70710678118654752f));
}
__device__ __forceinline__ void cp_async16(uint32_t dst, const void* src) {
    asm volatile("cp.async.cg.shared.global [%0], [%1], 16;" :: "r"(dst), "l"(src));
}

#define HSTR 20                     // half2 words per row (16 data + 4 pad) -> 80B, 16B-aligned
#define STG_WORDS (128 * HSTR)      // words per stage per operand
#define HG_SMEM (4 * STG_WORDS * 4) // 2 ops x 2 buffers = 40960 bytes

// EPI: 0=bias, 1=bias+GELU, 2=bias+residual, 3=bias+window-reverse-scatter+residual
// OUTH: output is fp16 (true) or fp32 (false)
template<int EPI, bool OUTH>
__global__ __launch_bounds__(128, 2)
void hgemm_kernel(const __half* __restrict__ A, const __half* __restrict__ Bt,
                  const float* __restrict__ bias, void* __restrict__ Cout,
                  const float* __restrict__ res, int M, int N, int K)
{
    extern __shared__ uint32_t sh[];    // half2 words
    uint32_t* As = sh;                  // [2][128][HSTR]
    uint32_t* Bs = sh + 2 * STG_WORDS;  // [2][128][HSTR]

    const int bx = blockIdx.x;          // N tile (128)
    const int by = blockIdx.y;          // M tile (128)
    const int tid = threadIdx.x;        // 128
    const int wid = tid >> 5, lane = tid & 31;
    const int wm = wid & 1;             // 2 warps in M (64 rows each)
    const int wn = wid >> 1;            // 2 warps in N (64 cols each)
    const int lr = lane >> 2;           // 0..7
    const int lc = lane & 3;            // 0..3

    float acc[4][8][4];
    #pragma unroll
    for (int i = 0; i < 4; i++)
        #pragma unroll
        for (int j = 0; j < 8; j++) {
            acc[i][j][0] = 0.f; acc[i][j][1] = 0.f;
            acc[i][j][2] = 0.f; acc[i][j][3] = 0.f;
        }

    // staging: thread -> its own row (A row, B row), 4 x 16B chunks (32 halves = k32)
    const __half* Ag = A  + (size_t)(by * 128 + tid) * K;
    const __half* Bg = Bt + (size_t)(bx * 128 + tid) * K;

    const int NS = K >> 5;              // K / 32

    // ---- prologue: stage 0 ----
    {
        uint32_t ad = (uint32_t)__cvta_generic_to_shared(As + tid * HSTR);
        uint32_t bd = (uint32_t)__cvta_generic_to_shared(Bs + tid * HSTR);
        #pragma unroll
        for (int c = 0; c < 4; c++) {
            cp_async16(ad + c * 16, Ag + c * 8);
            cp_async16(bd + c * 16, Bg + c * 8);
        }
        asm volatile("cp.async.commit_group;");
        asm volatile("cp.async.wait_group 0;");
    }
    __syncthreads();

    for (int s = 0; s < NS; s++) {
        if (s + 1 < NS) {
            const __half* Agn = Ag + (s + 1) * 32;
            const __half* Bgn = Bg + (s + 1) * 32;
            uint32_t ad = (uint32_t)__cvta_generic_to_shared(
                As + ((s + 1) & 1) * STG_WORDS + tid * HSTR);
            uint32_t bd = (uint32_t)__cvta_generic_to_shared(
                Bs + ((s + 1) & 1) * STG_WORDS + tid * HSTR);
            #pragma unroll
            for (int c = 0; c < 4; c++) {
                cp_async16(ad + c * 16, Agn + c * 8);
                cp_async16(bd + c * 16, Bgn + c * 8);
            }
            asm volatile("cp.async.commit_group;");
        }

        const uint32_t* Ab = As + (s & 1) * STG_WORDS;
        const uint32_t* Bb = Bs + (s & 1) * STG_WORDS;

        #pragma unroll
        for (int kk2 = 0; kk2 < 16; kk2 += 8) {     // two k=16 steps
            uint32_t af[4][4], bf[8][2];
            #pragma unroll
            for (int mi = 0; mi < 4; mi++) {
                int m = wm * 64 + mi * 16 + lr;
                af[mi][0] = Ab[(size_t)m * HSTR + kk2 + lc];
                af[mi][1] = Ab[(size_t)(m + 8) * HSTR + kk2 + lc];
                af[mi][2] = Ab[(size_t)m * HSTR + kk2 + lc + 4];
                af[mi][3] = Ab[(size_t)(m + 8) * HSTR + kk2 + lc + 4];
            }
            #pragma unroll
            for (int ni = 0; ni < 8; ni++) {
                int n = wn * 64 + ni * 8 + lr;
                bf[ni][0] = Bb[(size_t)n * HSTR + kk2 + lc];
                bf[ni][1] = Bb[(size_t)n * HSTR + kk2 + lc + 4];
            }
            #pragma unroll
            for (int mi = 0; mi < 4; mi++)
                #pragma unroll
                for (int ni = 0; ni < 8; ni++) {
                    asm volatile(
                        "mma.sync.aligned.m16n8k16.row.col.f32.f16.f16.f32 "
                        "{%0,%1,%2,%3}, {%4,%5,%6,%7}, {%8,%9}, {%0,%1,%2,%3};"
                        : "+f"(acc[mi][ni][0]), "+f"(acc[mi][ni][1]),
                          "+f"(acc[mi][ni][2]), "+f"(acc[mi][ni][3])
                        : "r"(af[mi][0]), "r"(af[mi][1]),
                          "r"(af[mi][2]), "r"(af[mi][3]),
                          "r"(bf[ni][0]), "r"(bf[ni][1]));
                }
        }

        if (s + 1 < NS) asm volatile("cp.async.wait_group 0;");
        __syncthreads();
    }

    // ---------------- epilogue ----------------
    const int m_base = by * 128 + wm * 64;
    const int n_base = bx * 128 + wn * 64;

    float2 bv[8];
    #pragma unroll
    for (int ni = 0; ni < 8; ni++)
        bv[ni] = *(const float2*)(bias + n_base + ni * 8 + 2 * lc);

    #pragma unroll
    for (int mi = 0; mi < 4; mi++) {
        int r0 = m_base + mi * 16 + lr;
        int r1 = r0 + 8;
        size_t orow0 = (size_t)r0, orow1 = (size_t)r1;
        if (EPI == 3) {
            int rows[2] = {r0, r1};
            size_t mapped[2];
            #pragma unroll
            for (int u = 0; u < 2; u++) {
                int t = rows[u];
                int b   = t / (NWIN * NTOK);
                int rem = t % (NWIN * NTOK);
                int win = rem / NTOK, pos = rem % NTOK;
                int wh = win >> 3, ww = win & 7;
                int p = pos / WSZ, q = pos % WSZ;
                int r = wh * WSZ + p + SSH; if (r >= HH) r -= HH;
                int c = ww * WSZ + q + SSH; if (c >= WW_) c -= WW_;
                mapped[u] = (size_t)(b * HH + r) * WW_ + c;
            }
            orow0 = mapped[0]; orow1 = mapped[1];
        }
        #pragma unroll
        for (int ni = 0; ni < 8; ni++) {
            int col = n_base + ni * 8 + 2 * lc;
            size_t off0 = orow0 * N + col;
            size_t off1 = orow1 * N + col;
            float2 v0, v1;
            v0.x = acc[mi][ni][0] + bv[ni].x;
            v0.y = acc[mi][ni][1] + bv[ni].y;
            v1.x = acc[mi][ni][2] + bv[ni].x;
            v1.y = acc[mi][ni][3] + bv[ni].y;
            if (EPI == 1) {
                v0.x = gelu_exact(v0.x); v0.y = gelu_exact(v0.y);
                v1.x = gelu_exact(v1.x); v1.y = gelu_exact(v1.y);
            }
            if (EPI == 2 || EPI == 3) {
                float2 q0 = *(const float2*)(res + off0);
                float2 q1 = *(const float2*)(res + off1);
                v0.x += q0.x; v0.y += q0.y;
                v1.x += q1.x; v1.y += q1.y;
            }
            if (OUTH) {
                __half* op = (__half*)Cout;
                *(__half2*)(op + off0) = __floats2half2_rn(v0.x, v0.y);
                *(__half2*)(op + off1) = __floats2half2_rn(v1.x, v1.y);
            } else {
                float* op = (float*)Cout;
                *(float2*)(op + off0) = v0;
                *(float2*)(op + off1) = v1;
            }
        }
    }
}

// ---------------- windowed attention (fp16 in/out, fp32 math) ----------------
__global__ void attn_kernel(const __half* __restrict__ qkv,
                            const float* __restrict__ rpb_table,
                            __half* __restrict__ o)
{
    int head = blockIdx.x;
    int win  = blockIdx.y;
    int wloc = win % NWIN;
    int wh = wloc / NWW, ww = wloc % NWW;

    __shared__ float Qs[NTOK][33];
    __shared__ float Ks[NTOK][33];
    __shared__ float Vs[NTOK][33];
    __shared__ float Ss[NTOK][NTOK];
    __shared__ float rpbs[169];
    __shared__ int   regn[NTOK];

    int tid = threadIdx.x;             // 128

    const __half* base = qkv + (size_t)win * NTOK * (3 * CC) + head * HD;
    for (int i = tid; i < NTOK * 8; i += 128) {
        int n = i >> 3, d4 = (i & 7) * 4;
        const __half* rp = base + (size_t)n * (3 * CC);
        float2 qa = __half22float2(*(const __half2*)(rp + d4));
        float2 qb = __half22float2(*(const __half2*)(rp + d4 + 2));
        float2 ka = __half22float2(*(const __half2*)(rp + CC + d4));
        float2 kb = __half22float2(*(const __half2*)(rp + CC + d4 + 2));
        float2 va = __half22float2(*(const __half2*)(rp + 2 * CC + d4));
        float2 vb = __half22float2(*(const __half2*)(rp + 2 * CC + d4 + 2));
        Qs[n][d4] = qa.x; Qs[n][d4+1] = qa.y; Qs[n][d4+2] = qb.x; Qs[n][d4+3] = qb.y;
        Ks[n][d4] = ka.x; Ks[n][d4+1] = ka.y; Ks[n][d4+2] = kb.x; Ks[n][d4+3] = kb.y;
        Vs[n][d4] = va.x; Vs[n][d4+1] = va.y; Vs[n][d4+2] = vb.x; Vs[n][d4+3] = vb.y;
    }
    for (int i = tid; i < 169; i += 128) rpbs[i] = rpb_table[i * NHEAD + head];
    if (tid < NTOK) {
        int p = tid / WSZ, q = tid % WSZ;
        int r = wh * WSZ + p, c = ww * WSZ + q;
        int rr = (r < 49) ? 0 : ((r < 53) ? 1 : 2);
        int rc = (c < 49) ? 0 : ((c < 53) ? 1 : 2);
        regn[tid] = rr * 3 + rc;
    }
    __syncthreads();

    for (int i = tid; i < NTOK * NTOK; i += 128) {
        int n = i / NTOK, m = i % NTOK;
        float acc = 0.0f;
        #pragma unroll
        for (int d = 0; d < HD; d++) acc += Qs[n][d] * Ks[m][d];
        int in_ = n / WSZ, jn = n % WSZ;
        int im  = m / WSZ, jm = m % WSZ;
        int ridx = (jn - jm + 6) * 13 + (in_ - im + 6);
        float val = acc * ATT_SCALE + rpbs[ridx];
        if (regn[n] != regn[m]) val -= 100.0f;
        Ss[n][m] = val;
    }
    __syncthreads();

    if (tid < NTOK) {
        float mx = -1e30f;
        #pragma unroll 7
        for (int m = 0; m < NTOK; m++) mx = fmaxf(mx, Ss[tid][m]);
        float sum = 0.0f;
        #pragma unroll 7
        for (int m = 0; m < NTOK; m++) {
            float e = expf(Ss[tid][m] - mx);
            Ss[tid][m] = e;
            sum += e;
        }
        float inv = 1.0f / sum;
        #pragma unroll 7
        for (int m = 0; m < NTOK; m++) Ss[tid][m] *= inv;
    }
    __syncthreads();

    __half* obase = o + (size_t)win * NTOK * CC + head * HD;
    for (int i = tid; i < NTOK * HD; i += 128) {
        int n = i >> 5, d = i & 31;
        float acc = 0.0f;
        #pragma unroll 7
        for (int m = 0; m < NTOK; m++) acc += Ss[n][m] * Vs[m][d];
        obase[(size_t)n * CC + d] = __float2half(acc);
    }
}

// ---------------- host launcher ----------------
extern "C" void kernel_launch(void* const* d_in, const int* in_sizes, int n_in,
                              void* d_out, int out_size)
{
    const float* x      = (const float*)d_in[0];
    const float* ln1_s  = (const float*)d_in[1];
    const float* ln1_b  = (const float*)d_in[2];
    const float* qkv_w  = (const float*)d_in[3];
    const float* qkv_b  = (const float*)d_in[4];
    const float* rpb    = (const float*)d_in[5];
    const float* proj_w = (const float*)d_in[6];
    const float* proj_b = (const float*)d_in[7];
    const float* ln2_s  = (const float*)d_in[8];
    const float* ln2_b  = (const float*)d_in[9];
    const float* fc1_w  = (const float*)d_in[10];
    const float* fc1_b  = (const float*)d_in[11];
    const float* fc2_w  = (const float*)d_in[12];
    const float* fc2_b  = (const float*)d_in[13];
    float* out = (float*)d_out;

    __half *ph, *pqkv, *po, *pact, *pwt;
    cudaGetSymbolAddress((void**)&ph,   g_h16);
    cudaGetSymbolAddress((void**)&pqkv, g_qkv16);
    cudaGetSymbolAddress((void**)&po,   g_o16);
    cudaGetSymbolAddress((void**)&pact, g_act16);
    cudaGetSymbolAddress((void**)&pwt,  g_wt);

    static int smem_set = 0;
    if (!smem_set) {
        cudaFuncSetAttribute(hgemm_kernel<0, true >, cudaFuncAttributeMaxDynamicSharedMemorySize, HG_SMEM);
        cudaFuncSetAttribute(hgemm_kernel<1, true >, cudaFuncAttributeMaxDynamicSharedMemorySize, HG_SMEM);
        cudaFuncSetAttribute(hgemm_kernel<2, false>, cudaFuncAttributeMaxDynamicSharedMemorySize, HG_SMEM);
        cudaFuncSetAttribute(hgemm_kernel<3, false>, cudaFuncAttributeMaxDynamicSharedMemorySize, HG_SMEM);
        smem_set = 1;
    }

    // 0. weight convert + transpose (fp32 [K][N] -> fp16 [N][K])
    wconv_kernel<<<dim3(1536/32, 512/32),  dim3(32, 8)>>>(qkv_w,  pwt + WQKV_OFF,  512,  1536);
    wconv_kernel<<<dim3(512/32,  512/32),  dim3(32, 8)>>>(proj_w, pwt + WPROJ_OFF, 512,  512);
    wconv_kernel<<<dim3(2048/32, 512/32),  dim3(32, 8)>>>(fc1_w,  pwt + WFC1_OFF,  512,  2048);
    wconv_kernel<<<dim3(512/32,  2048/32), dim3(32, 8)>>>(fc2_w,  pwt + WFC2_OFF,  2048, 512);

    // 1. LN1 + shift + window partition -> fp16
    ln_kernel<true><<<TOT, 128>>>(x, ln1_s, ln1_b, ph);
    // 2. QKV GEMM [50176,512]x[512,1536] -> fp16
    hgemm_kernel<0, true><<<dim3(1536/128, TOT/128), 128, HG_SMEM>>>(
        ph, pwt + WQKV_OFF, qkv_b, pqkv, nullptr, TOT, 1536, 512);
    // 3. windowed attention (fp16 io)
    attn_kernel<<<dim3(NHEAD, BB * NWIN), 128>>>(pqkv, rpb, po);
    // 4. proj GEMM + fused window-reverse scatter + residual -> f32 out
    hgemm_kernel<3, false><<<dim3(512/128, TOT/128), 128, HG_SMEM>>>(
        po, pwt + WPROJ_OFF, proj_b, out, x, TOT, 512, 512);
    // 5. LN2 -> fp16
    ln_kernel<false><<<TOT, 128>>>(out, ln2_s, ln2_b, ph);
    // 6. FC1 + GELU [50176,512]x[512,2048] -> fp16
    hgemm_kernel<1, true><<<dim3(HID/128, TOT/128), 128, HG_SMEM>>>(
        ph, pwt + WFC1_OFF, fc1_b, pact, nullptr, TOT, HID, 512);
    // 7. FC2 + residual [50176,2048]x[2048,512] -> f32 out
    hgemm_kernel<2, false><<<dim3(512/128, TOT/128), 128, HG_SMEM>>>(
        pact, pwt + WFC2_OFF, fc2_b, out, out, TOT, 512, HID);
}

// round 10
// speedup vs baseline: 1.4690x; 1.0770x over previous
#include <cuda_runtime.h>
#include <cuda_fp16.h>
#include <math.h>
#include <stdint.h>

// ---------------- problem constants ----------------
#define HH 56
#define WW_ 56
#define CC 512
#define NHEAD 16
#define WSZ 7
#define SSH 3
#define HID 2048
#define HD 32
#define NTOK 49
#define NWH 8
#define NWW 8
#define NWIN 64
#define BB 16
#define TOT (BB*HH*WW_)   // 50176 tokens
#define LN_EPS 1e-5f
#define ATT_SCALE 0.17677669529663687f

// ---------------- scratch (device globals, no allocs) ----------------
__device__ __align__(16) __half g_h16  [TOT * CC];
__device__ __align__(16) __half g_qkv16[TOT * 3 * CC];
__device__ __align__(16) __half g_o16  [TOT * CC];
__device__ __align__(16) __half g_act16[TOT * HID];
#define WQKV_OFF 0
#define WPROJ_OFF (512*1536)
#define WFC1_OFF  (WPROJ_OFF + 512*512)
#define WFC2_OFF  (WFC1_OFF + 512*2048)
__device__ __align__(16) __half g_wt[512*1536 + 512*512 + 512*2048 + 2048*512];

// ---------------- weight convert + transpose: W[K][N] f32 -> Wt[N][K] f16 ----------------
__global__ void wconv_kernel(const float* __restrict__ W, __half* __restrict__ Wt,
                             int K, int N)
{
    __shared__ float t[32][33];
    int nx = blockIdx.x * 32, ky = blockIdx.y * 32;
    int tx = threadIdx.x, ty = threadIdx.y;      // 32 x 8
    #pragma unroll
    for (int j = 0; j < 32; j += 8)
        t[ty + j][tx] = W[(size_t)(ky + ty + j) * N + nx + tx];
    __syncthreads();
    #pragma unroll
    for (int j = 0; j < 32; j += 8)
        Wt[(size_t)(nx + ty + j) * K + ky + tx] = __float2half(t[tx][ty + j]);
}

// ---------------- LayerNorm (optionally fused shift+window gather), fp16 out ----------------
template<bool GATHER>
__global__ void ln_kernel(const float* __restrict__ src,
                          const float* __restrict__ scale,
                          const float* __restrict__ bias,
                          __half* __restrict__ dst)
{
    int t = blockIdx.x;
    const float* sp;
    if (GATHER) {
        int b   = t / (NWIN * NTOK);
        int rem = t % (NWIN * NTOK);
        int win = rem / NTOK, pos = rem % NTOK;
        int wh = win / NWW, ww = win % NWW;
        int p = pos / WSZ, q = pos % WSZ;
        int row = (wh * WSZ + p + SSH) % HH;
        int col = (ww * WSZ + q + SSH) % WW_;
        sp = src + ((size_t)(b * HH + row) * WW_ + col) * CC;
    } else {
        sp = src + (size_t)t * CC;
    }
    __half* dp = dst + (size_t)t * CC;

    int tid = threadIdx.x;
    float4 v = *(const float4*)(sp + tid * 4);
    float s  = v.x + v.y + v.z + v.w;
    float s2 = v.x*v.x + v.y*v.y + v.z*v.z + v.w*v.w;

    __shared__ float red[8];
    #pragma unroll
    for (int off = 16; off > 0; off >>= 1) {
        s  += __shfl_down_sync(0xffffffffu, s,  off);
        s2 += __shfl_down_sync(0xffffffffu, s2, off);
    }
    int wid = tid >> 5, lane = tid & 31;
    if (lane == 0) { red[wid] = s; red[4 + wid] = s2; }
    __syncthreads();
    if (tid == 0) {
        float S  = red[0] + red[1] + red[2] + red[3];
        float S2 = red[4] + red[5] + red[6] + red[7];
        float mu  = S * (1.0f / CC);
        float var = S2 * (1.0f / CC) - mu * mu;
        red[0] = mu;
        red[1] = rsqrtf(var + LN_EPS);
    }
    __syncthreads();
    float mu = red[0], rs = red[1];
    float4 sc = *(const float4*)(scale + tid * 4);
    float4 bi = *(const float4*)(bias  + tid * 4);
    float ox = (v.x - mu) * rs * sc.x + bi.x;
    float oy = (v.y - mu) * rs * sc.y + bi.y;
    float oz = (v.z - mu) * rs * sc.z + bi.z;
    float ow = (v.w - mu) * rs * sc.w + bi.w;
    *(__half2*)(dp + tid * 4)     = __floats2half2_rn(ox, oy);
    *(__half2*)(dp + tid * 4 + 2) = __floats2half2_rn(oz, ow);
}

// ---------------- fp16 tensor-core GEMM, 4-stage pipeline + ldmatrix ----------------
__device__ __forceinline__ float gelu_exact(float x) {
    return 0.5f * x * (1.0f + erff(x * 0.70710678118654752f));
}
__device__ __forceinline__ void cp_async16(uint32_t dst, const void* src) {
    asm volatile("cp.async.cg.shared.global [%0], [%1], 16;" :: "r"(dst), "l"(src));
}
__device__ __forceinline__ void ldsm_x4(uint32_t& r0, uint32_t& r1,
                                        uint32_t& r2, uint32_t& r3, uint32_t addr) {
    asm volatile("ldmatrix.sync.aligned.m8n8.x4.shared.b16 {%0,%1,%2,%3}, [%4];"
                 : "=r"(r0), "=r"(r1), "=r"(r2), "=r"(r3) : "r"(addr));
}

#define HSTR 20                     // half2 words per row (16 data + 4 pad) -> 80B
#define NSTG 4                      // pipeline stages
#define STG_WORDS (128 * HSTR)      // words per stage per operand
#define HG_SMEM (2 * NSTG * STG_WORDS * 4)   // 81920 bytes

// EPI: 0=bias, 1=bias+GELU, 2=bias+residual, 3=bias+window-reverse-scatter+residual
template<int EPI, bool OUTH>
__global__ __launch_bounds__(128, 2)
void hgemm_kernel(const __half* __restrict__ A, const __half* __restrict__ Bt,
                  const float* __restrict__ bias, void* __restrict__ Cout,
                  const float* __restrict__ res, int M, int N, int K)
{
    extern __shared__ uint32_t sh[];            // half2 words
    uint32_t* As = sh;                          // [NSTG][128][HSTR]
    uint32_t* Bs = sh + NSTG * STG_WORDS;       // [NSTG][128][HSTR]

    const int bx = blockIdx.x;
    const int by = blockIdx.y;
    const int tid = threadIdx.x;                // 128
    const int wid = tid >> 5, lane = tid & 31;
    const int wm = wid & 1;                     // 2 warps in M (64 rows)
    const int wn = wid >> 1;                    // 2 warps in N (64 cols)
    const int lr = lane >> 2;
    const int lc = lane & 3;
    const int sub  = lane >> 3;                 // 0..3 (ldmatrix address group)
    const int srow = lane & 7;

    float acc[4][8][4];
    #pragma unroll
    for (int i = 0; i < 4; i++)
        #pragma unroll
        for (int j = 0; j < 8; j++) {
            acc[i][j][0] = 0.f; acc[i][j][1] = 0.f;
            acc[i][j][2] = 0.f; acc[i][j][3] = 0.f;
        }

    const __half* Ag = A  + (size_t)(by * 128 + tid) * K;
    const __half* Bg = Bt + (size_t)(bx * 128 + tid) * K;
    const int NS = K >> 5;                      // stages of k32

    // per-thread ldmatrix offsets (in words)
    int a_row_off[4], b_row_off[4];
    #pragma unroll
    for (int mi = 0; mi < 4; mi++)
        a_row_off[mi] = (wm * 64 + mi * 16 + (sub & 1) * 8 + srow) * HSTR + (sub >> 1) * 4;
    #pragma unroll
    for (int p = 0; p < 4; p++)
        b_row_off[p] = (wn * 64 + p * 16 + (sub >> 1) * 8 + srow) * HSTR + (sub & 1) * 4;

    // ---- prologue: stages 0..2 ----
    #pragma unroll
    for (int p = 0; p < NSTG - 1; p++) {
        uint32_t ad = (uint32_t)__cvta_generic_to_shared(As + p * STG_WORDS + tid * HSTR);
        uint32_t bd = (uint32_t)__cvta_generic_to_shared(Bs + p * STG_WORDS + tid * HSTR);
        const __half* Agp = Ag + p * 32;
        const __half* Bgp = Bg + p * 32;
        #pragma unroll
        for (int c = 0; c < 4; c++) {
            cp_async16(ad + c * 16, Agp + c * 8);
            cp_async16(bd + c * 16, Bgp + c * 8);
        }
        asm volatile("cp.async.commit_group;");
    }

    for (int s = 0; s < NS; s++) {
        // group s complete (up to NSTG-2 newer groups may still be pending)
        asm volatile("cp.async.wait_group %0;" :: "n"(NSTG - 2));
        __syncthreads();   // data visible to all; all warps done reading buf (s-1)%NSTG

        // prefetch stage s+NSTG-1 into buf (s-1)%NSTG
        if (s + NSTG - 1 < NS) {
            int p = s + NSTG - 1;
            int buf = p & (NSTG - 1);
            uint32_t ad = (uint32_t)__cvta_generic_to_shared(As + buf * STG_WORDS + tid * HSTR);
            uint32_t bd = (uint32_t)__cvta_generic_to_shared(Bs + buf * STG_WORDS + tid * HSTR);
            const __half* Agp = Ag + p * 32;
            const __half* Bgp = Bg + p * 32;
            #pragma unroll
            for (int c = 0; c < 4; c++) {
                cp_async16(ad + c * 16, Agp + c * 8);
                cp_async16(bd + c * 16, Bgp + c * 8);
            }
            asm volatile("cp.async.commit_group;");
        }

        const int buf = s & (NSTG - 1);
        const uint32_t abase = (uint32_t)__cvta_generic_to_shared(As + buf * STG_WORDS);
        const uint32_t bbase = (uint32_t)__cvta_generic_to_shared(Bs + buf * STG_WORDS);

        #pragma unroll
        for (int kk2 = 0; kk2 < 16; kk2 += 8) {     // two k16 steps
            uint32_t af[4][4], bf[8][2];
            #pragma unroll
            for (int mi = 0; mi < 4; mi++)
                ldsm_x4(af[mi][0], af[mi][1], af[mi][2], af[mi][3],
                        abase + (uint32_t)((a_row_off[mi] + kk2) << 2));
            #pragma unroll
            for (int p = 0; p < 4; p++)
                ldsm_x4(bf[2*p][0], bf[2*p][1], bf[2*p+1][0], bf[2*p+1][1],
                        bbase + (uint32_t)((b_row_off[p] + kk2) << 2));
            #pragma unroll
            for (int mi = 0; mi < 4; mi++)
                #pragma unroll
                for (int ni = 0; ni < 8; ni++) {
                    asm volatile(
                        "mma.sync.aligned.m16n8k16.row.col.f32.f16.f16.f32 "
                        "{%0,%1,%2,%3}, {%4,%5,%6,%7}, {%8,%9}, {%0,%1,%2,%3};"
                        : "+f"(acc[mi][ni][0]), "+f"(acc[mi][ni][1]),
                          "+f"(acc[mi][ni][2]), "+f"(acc[mi][ni][3])
                        : "r"(af[mi][0]), "r"(af[mi][1]),
                          "r"(af[mi][2]), "r"(af[mi][3]),
                          "r"(bf[ni][0]), "r"(bf[ni][1]));
                }
        }
    }

    // ---------------- epilogue ----------------
    const int m_base = by * 128 + wm * 64;
    const int n_base = bx * 128 + wn * 64;

    float2 bv[8];
    #pragma unroll
    for (int ni = 0; ni < 8; ni++)
        bv[ni] = *(const float2*)(bias + n_base + ni * 8 + 2 * lc);

    #pragma unroll
    for (int mi = 0; mi < 4; mi++) {
        int r0 = m_base + mi * 16 + lr;
        int r1 = r0 + 8;
        size_t orow0 = (size_t)r0, orow1 = (size_t)r1;
        if (EPI == 3) {
            int rows[2] = {r0, r1};
            size_t mapped[2];
            #pragma unroll
            for (int u = 0; u < 2; u++) {
                int t = rows[u];
                int b   = t / (NWIN * NTOK);
                int rem = t % (NWIN * NTOK);
                int win = rem / NTOK, pos = rem % NTOK;
                int wh = win >> 3, ww = win & 7;
                int p = pos / WSZ, q = pos % WSZ;
                int r = wh * WSZ + p + SSH; if (r >= HH) r -= HH;
                int c = ww * WSZ + q + SSH; if (c >= WW_) c -= WW_;
                mapped[u] = (size_t)(b * HH + r) * WW_ + c;
            }
            orow0 = mapped[0]; orow1 = mapped[1];
        }
        #pragma unroll
        for (int ni = 0; ni < 8; ni++) {
            int col = n_base + ni * 8 + 2 * lc;
            size_t off0 = orow0 * N + col;
            size_t off1 = orow1 * N + col;
            float2 v0, v1;
            v0.x = acc[mi][ni][0] + bv[ni].x;
            v0.y = acc[mi][ni][1] + bv[ni].y;
            v1.x = acc[mi][ni][2] + bv[ni].x;
            v1.y = acc[mi][ni][3] + bv[ni].y;
            if (EPI == 1) {
                v0.x = gelu_exact(v0.x); v0.y = gelu_exact(v0.y);
                v1.x = gelu_exact(v1.x); v1.y = gelu_exact(v1.y);
            }
            if (EPI == 2 || EPI == 3) {
                float2 q0 = *(const float2*)(res + off0);
                float2 q1 = *(const float2*)(res + off1);
                v0.x += q0.x; v0.y += q0.y;
                v1.x += q1.x; v1.y += q1.y;
            }
            if (OUTH) {
                __half* op = (__half*)Cout;
                *(__half2*)(op + off0) = __floats2half2_rn(v0.x, v0.y);
                *(__half2*)(op + off1) = __floats2half2_rn(v1.x, v1.y);
            } else {
                float* op = (float*)Cout;
                *(float2*)(op + off0) = v0;
                *(float2*)(op + off1) = v1;
            }
        }
    }
}

// ---------------- windowed attention (fp16 in/out, fp32 math) ----------------
__global__ void attn_kernel(const __half* __restrict__ qkv,
                            const float* __restrict__ rpb_table,
                            __half* __restrict__ o)
{
    int head = blockIdx.x;
    int win  = blockIdx.y;
    int wloc = win % NWIN;
    int wh = wloc / NWW, ww = wloc % NWW;

    __shared__ float Qs[NTOK][33];
    __shared__ float Ks[NTOK][33];
    __shared__ float Vs[NTOK][33];
    __shared__ float Ss[NTOK][NTOK];
    __shared__ float rpbs[169];
    __shared__ int   regn[NTOK];

    int tid = threadIdx.x;

    const __half* base = qkv + (size_t)win * NTOK * (3 * CC) + head * HD;
    for (int i = tid; i < NTOK * 8; i += 128) {
        int n = i >> 3, d4 = (i & 7) * 4;
        const __half* rp = base + (size_t)n * (3 * CC);
        float2 qa = __half22float2(*(const __half2*)(rp + d4));
        float2 qb = __half22float2(*(const __half2*)(rp + d4 + 2));
        float2 ka = __half22float2(*(const __half2*)(rp + CC + d4));
        float2 kb = __half22float2(*(const __half2*)(rp + CC + d4 + 2));
        float2 va = __half22float2(*(const __half2*)(rp + 2 * CC + d4));
        float2 vb = __half22float2(*(const __half2*)(rp + 2 * CC + d4 + 2));
        Qs[n][d4] = qa.x; Qs[n][d4+1] = qa.y; Qs[n][d4+2] = qb.x; Qs[n][d4+3] = qb.y;
        Ks[n][d4] = ka.x; Ks[n][d4+1] = ka.y; Ks[n][d4+2] = kb.x; Ks[n][d4+3] = kb.y;
        Vs[n][d4] = va.x; Vs[n][d4+1] = va.y; Vs[n][d4+2] = vb.x; Vs[n][d4+3] = vb.y;
    }
    for (int i = tid; i < 169; i += 128) rpbs[i] = rpb_table[i * NHEAD + head];
    if (tid < NTOK) {
        int p = tid / WSZ, q = tid % WSZ;
        int r = wh * WSZ + p, c = ww * WSZ + q;
        int rr = (r < 49) ? 0 : ((r < 53) ? 1 : 2);
        int rc = (c < 49) ? 0 : ((c < 53) ? 1 : 2);
        regn[tid] = rr * 3 + rc;
    }
    __syncthreads();

    for (int i = tid; i < NTOK * NTOK; i += 128) {
        int n = i / NTOK, m = i % NTOK;
        float acc = 0.0f;
        #pragma unroll
        for (int d = 0; d < HD; d++) acc += Qs[n][d] * Ks[m][d];
        int in_ = n / WSZ, jn = n % WSZ;
        int im  = m / WSZ, jm = m % WSZ;
        int ridx = (jn - jm + 6) * 13 + (in_ - im + 6);
        float val = acc * ATT_SCALE + rpbs[ridx];
        if (regn[n] != regn[m]) val -= 100.0f;
        Ss[n][m] = val;
    }
    __syncthreads();

    if (tid < NTOK) {
        float mx = -1e30f;
        #pragma unroll 7
        for (int m = 0; m < NTOK; m++) mx = fmaxf(mx, Ss[tid][m]);
        float sum = 0.0f;
        #pragma unroll 7
        for (int m = 0; m < NTOK; m++) {
            float e = expf(Ss[tid][m] - mx);
            Ss[tid][m] = e;
            sum += e;
        }
        float inv = 1.0f / sum;
        #pragma unroll 7
        for (int m = 0; m < NTOK; m++) Ss[tid][m] *= inv;
    }
    __syncthreads();

    __half* obase = o + (size_t)win * NTOK * CC + head * HD;
    for (int i = tid; i < NTOK * HD; i += 128) {
        int n = i >> 5, d = i & 31;
        float acc = 0.0f;
        #pragma unroll 7
        for (int m = 0; m < NTOK; m++) acc += Ss[n][m] * Vs[m][d];
        obase[(size_t)n * CC + d] = __float2half(acc);
    }
}

// ---------------- host launcher ----------------
extern "C" void kernel_launch(void* const* d_in, const int* in_sizes, int n_in,
                              void* d_out, int out_size)
{
    const float* x      = (const float*)d_in[0];
    const float* ln1_s  = (const float*)d_in[1];
    const float* ln1_b  = (const float*)d_in[2];
    const float* qkv_w  = (const float*)d_in[3];
    const float* qkv_b  = (const float*)d_in[4];
    const float* rpb    = (const float*)d_in[5];
    const float* proj_w = (const float*)d_in[6];
    const float* proj_b = (const float*)d_in[7];
    const float* ln2_s  = (const float*)d_in[8];
    const float* ln2_b  = (const float*)d_in[9];
    const float* fc1_w  = (const float*)d_in[10];
    const float* fc1_b  = (const float*)d_in[11];
    const float* fc2_w  = (const float*)d_in[12];
    const float* fc2_b  = (const float*)d_in[13];
    float* out = (float*)d_out;

    __half *ph, *pqkv, *po, *pact, *pwt;
    cudaGetSymbolAddress((void**)&ph,   g_h16);
    cudaGetSymbolAddress((void**)&pqkv, g_qkv16);
    cudaGetSymbolAddress((void**)&po,   g_o16);
    cudaGetSymbolAddress((void**)&pact, g_act16);
    cudaGetSymbolAddress((void**)&pwt,  g_wt);

    static int smem_set = 0;
    if (!smem_set) {
        cudaFuncSetAttribute(hgemm_kernel<0, true >, cudaFuncAttributeMaxDynamicSharedMemorySize, HG_SMEM);
        cudaFuncSetAttribute(hgemm_kernel<1, true >, cudaFuncAttributeMaxDynamicSharedMemorySize, HG_SMEM);
        cudaFuncSetAttribute(hgemm_kernel<2, false>, cudaFuncAttributeMaxDynamicSharedMemorySize, HG_SMEM);
        cudaFuncSetAttribute(hgemm_kernel<3, false>, cudaFuncAttributeMaxDynamicSharedMemorySize, HG_SMEM);
        smem_set = 1;
    }

    // 0. weight convert + transpose (fp32 [K][N] -> fp16 [N][K])
    wconv_kernel<<<dim3(1536/32, 512/32),  dim3(32, 8)>>>(qkv_w,  pwt + WQKV_OFF,  512,  1536);
    wconv_kernel<<<dim3(512/32,  512/32),  dim3(32, 8)>>>(proj_w, pwt + WPROJ_OFF, 512,  512);
    wconv_kernel<<<dim3(2048/32, 512/32),  dim3(32, 8)>>>(fc1_w,  pwt + WFC1_OFF,  512,  2048);
    wconv_kernel<<<dim3(512/32,  2048/32), dim3(32, 8)>>>(fc2_w,  pwt + WFC2_OFF,  2048, 512);

    // 1. LN1 + shift + window partition -> fp16
    ln_kernel<true><<<TOT, 128>>>(x, ln1_s, ln1_b, ph);
    // 2. QKV GEMM [50176,512]x[512,1536] -> fp16
    hgemm_kernel<0, true><<<dim3(1536/128, TOT/128), 128, HG_SMEM>>>(
        ph, pwt + WQKV_OFF, qkv_b, pqkv, nullptr, TOT, 1536, 512);
    // 3. windowed attention (fp16 io)
    attn_kernel<<<dim3(NHEAD, BB * NWIN), 128>>>(pqkv, rpb, po);
    // 4. proj GEMM + fused window-reverse scatter + residual -> f32 out
    hgemm_kernel<3, false><<<dim3(512/128, TOT/128), 128, HG_SMEM>>>(
        po, pwt + WPROJ_OFF, proj_b, out, x, TOT, 512, 512);
    // 5. LN2 -> fp16
    ln_kernel<false><<<TOT, 128>>>(out, ln2_s, ln2_b, ph);
    // 6. FC1 + GELU [50176,512]x[512,2048] -> fp16
    hgemm_kernel<1, true><<<dim3(HID/128, TOT/128), 128, HG_SMEM>>>(
        ph, pwt + WFC1_OFF, fc1_b, pact, nullptr, TOT, HID, 512);
    // 7. FC2 + residual [50176,2048]x[2048,512] -> f32 out
    hgemm_kernel<2, false><<<dim3(512/128, TOT/128), 128, HG_SMEM>>>(
        pact, pwt + WFC2_OFF, fc2_b, out, out, TOT, 512, HID);
}

// round 11
// speedup vs baseline: 1.9232x; 1.3092x over previous
#include <cuda_runtime.h>
#include <cuda_fp16.h>
#include <math.h>
#include <stdint.h>

// ---------------- problem constants ----------------
#define HH 56
#define WW_ 56
#define CC 512
#define NHEAD 16
#define WSZ 7
#define SSH 3
#define HID 2048
#define HD 32
#define NTOK 49
#define NWH 8
#define NWW 8
#define NWIN 64
#define BB 16
#define TOT (BB*HH*WW_)   // 50176 tokens
#define LN_EPS 1e-5f
#define ATT_SCALE 0.17677669529663687f
#define DIV7(x) (((x) * 9363) >> 16)    // exact for 0..63

// ---------------- scratch (device globals, no allocs) ----------------
__device__ __align__(16) __half g_h16  [TOT * CC];
__device__ __align__(16) __half g_qkv16[TOT * 3 * CC];
__device__ __align__(16) __half g_o16  [TOT * CC];
__device__ __align__(16) __half g_act16[TOT * HID];
#define WQKV_OFF 0
#define WPROJ_OFF (512*1536)
#define WFC1_OFF  (WPROJ_OFF + 512*512)
#define WFC2_OFF  (WFC1_OFF + 512*2048)
__device__ __align__(16) __half g_wt[512*1536 + 512*512 + 512*2048 + 2048*512];

// ---------------- common helpers ----------------
__device__ __forceinline__ void cp_async16(uint32_t dst, const void* src) {
    asm volatile("cp.async.cg.shared.global [%0], [%1], 16;" :: "r"(dst), "l"(src));
}
__device__ __forceinline__ void ldsm_x4(uint32_t& r0, uint32_t& r1,
                                        uint32_t& r2, uint32_t& r3, uint32_t addr) {
    asm volatile("ldmatrix.sync.aligned.m8n8.x4.shared.b16 {%0,%1,%2,%3}, [%4];"
                 : "=r"(r0), "=r"(r1), "=r"(r2), "=r"(r3) : "r"(addr));
}
__device__ __forceinline__ void ldsm_x4_t(uint32_t& r0, uint32_t& r1,
                                          uint32_t& r2, uint32_t& r3, uint32_t addr) {
    asm volatile("ldmatrix.sync.aligned.m8n8.x4.trans.shared.b16 {%0,%1,%2,%3}, [%4];"
                 : "=r"(r0), "=r"(r1), "=r"(r2), "=r"(r3) : "r"(addr));
}
__device__ __forceinline__ void mma16816(float* c, const uint32_t* a, const uint32_t* b) {
    asm volatile(
        "mma.sync.aligned.m16n8k16.row.col.f32.f16.f16.f32 "
        "{%0,%1,%2,%3}, {%4,%5,%6,%7}, {%8,%9}, {%0,%1,%2,%3};"
        : "+f"(c[0]), "+f"(c[1]), "+f"(c[2]), "+f"(c[3])
        : "r"(a[0]), "r"(a[1]), "r"(a[2]), "r"(a[3]), "r"(b[0]), "r"(b[1]));
}
__device__ __forceinline__ uint32_t packh2(float a, float b) {
    __half2 h = __floats2half2_rn(a, b);
    return *(uint32_t*)&h;
}
__device__ __forceinline__ float gelu_exact(float x) {
    return 0.5f * x * (1.0f + erff(x * 0.70710678118654752f));
}

// ---------------- weight convert + transpose: W[K][N] f32 -> Wt[N][K] f16 ----------------
__global__ void wconv_kernel(const float* __restrict__ W, __half* __restrict__ Wt,
                             int K, int N)
{
    __shared__ float t[32][33];
    int nx = blockIdx.x * 32, ky = blockIdx.y * 32;
    int tx = threadIdx.x, ty = threadIdx.y;      // 32 x 8
    #pragma unroll
    for (int j = 0; j < 32; j += 8)
        t[ty + j][tx] = W[(size_t)(ky + ty + j) * N + nx + tx];
    __syncthreads();
    #pragma unroll
    for (int j = 0; j < 32; j += 8)
        Wt[(size_t)(nx + ty + j) * K + ky + tx] = __float2half(t[tx][ty + j]);
}

// ---------------- LayerNorm (optionally fused shift+window gather), fp16 out ----------------
template<bool GATHER>
__global__ void ln_kernel(const float* __restrict__ src,
                          const float* __restrict__ scale,
                          const float* __restrict__ bias,
                          __half* __restrict__ dst)
{
    int t = blockIdx.x;
    const float* sp;
    if (GATHER) {
        int b   = t / (NWIN * NTOK);
        int rem = t % (NWIN * NTOK);
        int win = rem / NTOK, pos = rem % NTOK;
        int wh = win / NWW, ww = win % NWW;
        int p = pos / WSZ, q = pos % WSZ;
        int row = (wh * WSZ + p + SSH) % HH;
        int col = (ww * WSZ + q + SSH) % WW_;
        sp = src + ((size_t)(b * HH + row) * WW_ + col) * CC;
    } else {
        sp = src + (size_t)t * CC;
    }
    __half* dp = dst + (size_t)t * CC;

    int tid = threadIdx.x;
    float4 v = *(const float4*)(sp + tid * 4);
    float s  = v.x + v.y + v.z + v.w;
    float s2 = v.x*v.x + v.y*v.y + v.z*v.z + v.w*v.w;

    __shared__ float red[8];
    #pragma unroll
    for (int off = 16; off > 0; off >>= 1) {
        s  += __shfl_down_sync(0xffffffffu, s,  off);
        s2 += __shfl_down_sync(0xffffffffu, s2, off);
    }
    int wid = tid >> 5, lane = tid & 31;
    if (lane == 0) { red[wid] = s; red[4 + wid] = s2; }
    __syncthreads();
    if (tid == 0) {
        float S  = red[0] + red[1] + red[2] + red[3];
        float S2 = red[4] + red[5] + red[6] + red[7];
        float mu  = S * (1.0f / CC);
        float var = S2 * (1.0f / CC) - mu * mu;
        red[0] = mu;
        red[1] = rsqrtf(var + LN_EPS);
    }
    __syncthreads();
    float mu = red[0], rs = red[1];
    float4 sc = *(const float4*)(scale + tid * 4);
    float4 bi = *(const float4*)(bias  + tid * 4);
    float ox = (v.x - mu) * rs * sc.x + bi.x;
    float oy = (v.y - mu) * rs * sc.y + bi.y;
    float oz = (v.z - mu) * rs * sc.z + bi.z;
    float ow = (v.w - mu) * rs * sc.w + bi.w;
    *(__half2*)(dp + tid * 4)     = __floats2half2_rn(ox, oy);
    *(__half2*)(dp + tid * 4 + 2) = __floats2half2_rn(oz, ow);
}

// ---------------- fp16 tensor-core GEMM, 4-stage pipeline + ldmatrix ----------------
#define HSTR 20                     // half2 words per row (16 data + 4 pad) -> 80B
#define NSTG 4
#define STG_WORDS (128 * HSTR)
#define HG_SMEM (2 * NSTG * STG_WORDS * 4)   // 81920 bytes

template<int EPI, bool OUTH>
__global__ __launch_bounds__(128, 2)
void hgemm_kernel(const __half* __restrict__ A, const __half* __restrict__ Bt,
                  const float* __restrict__ bias, void* __restrict__ Cout,
                  const float* __restrict__ res, int M, int N, int K)
{
    extern __shared__ uint32_t sh[];
    uint32_t* As = sh;
    uint32_t* Bs = sh + NSTG * STG_WORDS;

    const int bx = blockIdx.x;
    const int by = blockIdx.y;
    const int tid = threadIdx.x;
    const int wid = tid >> 5, lane = tid & 31;
    const int wm = wid & 1;
    const int wn = wid >> 1;
    const int lr = lane >> 2;
    const int lc = lane & 3;
    const int sub  = lane >> 3;
    const int srow = lane & 7;

    float acc[4][8][4];
    #pragma unroll
    for (int i = 0; i < 4; i++)
        #pragma unroll
        for (int j = 0; j < 8; j++) {
            acc[i][j][0] = 0.f; acc[i][j][1] = 0.f;
            acc[i][j][2] = 0.f; acc[i][j][3] = 0.f;
        }

    const __half* Ag = A  + (size_t)(by * 128 + tid) * K;
    const __half* Bg = Bt + (size_t)(bx * 128 + tid) * K;
    const int NS = K >> 5;

    int a_row_off[4], b_row_off[4];
    #pragma unroll
    for (int mi = 0; mi < 4; mi++)
        a_row_off[mi] = (wm * 64 + mi * 16 + (sub & 1) * 8 + srow) * HSTR + (sub >> 1) * 4;
    #pragma unroll
    for (int p = 0; p < 4; p++)
        b_row_off[p] = (wn * 64 + p * 16 + (sub >> 1) * 8 + srow) * HSTR + (sub & 1) * 4;

    #pragma unroll
    for (int p = 0; p < NSTG - 1; p++) {
        uint32_t ad = (uint32_t)__cvta_generic_to_shared(As + p * STG_WORDS + tid * HSTR);
        uint32_t bd = (uint32_t)__cvta_generic_to_shared(Bs + p * STG_WORDS + tid * HSTR);
        const __half* Agp = Ag + p * 32;
        const __half* Bgp = Bg + p * 32;
        #pragma unroll
        for (int c = 0; c < 4; c++) {
            cp_async16(ad + c * 16, Agp + c * 8);
            cp_async16(bd + c * 16, Bgp + c * 8);
        }
        asm volatile("cp.async.commit_group;");
    }

    for (int s = 0; s < NS; s++) {
        asm volatile("cp.async.wait_group %0;" :: "n"(NSTG - 2));
        __syncthreads();

        if (s + NSTG - 1 < NS) {
            int p = s + NSTG - 1;
            int buf = p & (NSTG - 1);
            uint32_t ad = (uint32_t)__cvta_generic_to_shared(As + buf * STG_WORDS + tid * HSTR);
            uint32_t bd = (uint32_t)__cvta_generic_to_shared(Bs + buf * STG_WORDS + tid * HSTR);
            const __half* Agp = Ag + p * 32;
            const __half* Bgp = Bg + p * 32;
            #pragma unroll
            for (int c = 0; c < 4; c++) {
                cp_async16(ad + c * 16, Agp + c * 8);
                cp_async16(bd + c * 16, Bgp + c * 8);
            }
            asm volatile("cp.async.commit_group;");
        }

        const int buf = s & (NSTG - 1);
        const uint32_t abase = (uint32_t)__cvta_generic_to_shared(As + buf * STG_WORDS);
        const uint32_t bbase = (uint32_t)__cvta_generic_to_shared(Bs + buf * STG_WORDS);

        #pragma unroll
        for (int kk2 = 0; kk2 < 16; kk2 += 8) {
            uint32_t af[4][4], bf[8][2];
            #pragma unroll
            for (int mi = 0; mi < 4; mi++)
                ldsm_x4(af[mi][0], af[mi][1], af[mi][2], af[mi][3],
                        abase + (uint32_t)((a_row_off[mi] + kk2) << 2));
            #pragma unroll
            for (int p = 0; p < 4; p++)
                ldsm_x4(bf[2*p][0], bf[2*p][1], bf[2*p+1][0], bf[2*p+1][1],
                        bbase + (uint32_t)((b_row_off[p] + kk2) << 2));
            #pragma unroll
            for (int mi = 0; mi < 4; mi++)
                #pragma unroll
                for (int ni = 0; ni < 8; ni++)
                    mma16816(acc[mi][ni], af[mi], bf[ni]);
        }
    }

    // epilogue
    const int m_base = by * 128 + wm * 64;
    const int n_base = bx * 128 + wn * 64;

    float2 bv[8];
    #pragma unroll
    for (int ni = 0; ni < 8; ni++)
        bv[ni] = *(const float2*)(bias + n_base + ni * 8 + 2 * lc);

    #pragma unroll
    for (int mi = 0; mi < 4; mi++) {
        int r0 = m_base + mi * 16 + lr;
        int r1 = r0 + 8;
        size_t orow0 = (size_t)r0, orow1 = (size_t)r1;
        if (EPI == 3) {
            int rows[2] = {r0, r1};
            size_t mapped[2];
            #pragma unroll
            for (int u = 0; u < 2; u++) {
                int t = rows[u];
                int b   = t / (NWIN * NTOK);
                int rem = t % (NWIN * NTOK);
                int win = rem / NTOK, pos = rem % NTOK;
                int wh = win >> 3, ww = win & 7;
                int p = pos / WSZ, q = pos % WSZ;
                int r = wh * WSZ + p + SSH; if (r >= HH) r -= HH;
                int c = ww * WSZ + q + SSH; if (c >= WW_) c -= WW_;
                mapped[u] = (size_t)(b * HH + r) * WW_ + c;
            }
            orow0 = mapped[0]; orow1 = mapped[1];
        }
        #pragma unroll
        for (int ni = 0; ni < 8; ni++) {
            int col = n_base + ni * 8 + 2 * lc;
            size_t off0 = orow0 * N + col;
            size_t off1 = orow1 * N + col;
            float2 v0, v1;
            v0.x = acc[mi][ni][0] + bv[ni].x;
            v0.y = acc[mi][ni][1] + bv[ni].y;
            v1.x = acc[mi][ni][2] + bv[ni].x;
            v1.y = acc[mi][ni][3] + bv[ni].y;
            if (EPI == 1) {
                v0.x = gelu_exact(v0.x); v0.y = gelu_exact(v0.y);
                v1.x = gelu_exact(v1.x); v1.y = gelu_exact(v1.y);
            }
            if (EPI == 2 || EPI == 3) {
                float2 q0 = *(const float2*)(res + off0);
                float2 q1 = *(const float2*)(res + off1);
                v0.x += q0.x; v0.y += q0.y;
                v1.x += q1.x; v1.y += q1.y;
            }
            if (OUTH) {
                __half* op = (__half*)Cout;
                *(__half2*)(op + off0) = __floats2half2_rn(v0.x, v0.y);
                *(__half2*)(op + off1) = __floats2half2_rn(v1.x, v1.y);
            } else {
                float* op = (float*)Cout;
                *(float2*)(op + off0) = v0;
                *(float2*)(op + off1) = v1;
            }
        }
    }
}

// ---------------- tensor-core windowed attention ----------------
// grid = 1024 windows, 256 threads (8 warps); warp handles heads 2w, 2w+1
// per-warp smem tiles: Q,K,V each [64 rows][40 halves] (80B rows, ldmatrix-friendly)
#define ATT_TILE 2560                        // halves per tile
#define ATT_SMEM (8*3*ATT_TILE*2 + 16*172*4 + 64*4)

__global__ __launch_bounds__(256, 1)
void attn_mma_kernel(const __half* __restrict__ qkv,
                     const float* __restrict__ rpb_table,
                     __half* __restrict__ o)
{
    extern __shared__ __half smha[];
    __half* tiles = smha;                             // 8*3*2560 halves
    float*  rpbs  = (float*)(smha + 8*3*ATT_TILE);    // [16][172] (pad zeroed)
    int*    regn  = (int*)(rpbs + 16*172);            // [64]

    const int win = blockIdx.x;
    const int wloc = win & 63;
    const int wh = wloc >> 3, ww = wloc & 7;
    const int tid = threadIdx.x;
    const int warp = tid >> 5, lane = tid & 31;
    const int lr = lane >> 2, lc = lane & 3;
    const int sub = lane >> 3, srow = lane & 7;

    // rpb transpose load + zero pad
    for (int i = tid; i < 16 * 172; i += 256) {
        int h = i / 172, r = i % 172;
        rpbs[i] = (r < 169) ? rpb_table[r * 16 + h] : 0.0f;
    }
    if (tid < 64) {
        int p = DIV7(tid), q = tid - 7 * p;
        int r = wh * 7 + p, c = ww * 7 + q;
        int rr = (r < 49) ? 0 : ((r < 53) ? 1 : 2);
        int rc = (c < 49) ? 0 : ((c < 53) ? 1 : 2);
        regn[tid] = rr * 3 + rc;
    }
    __syncthreads();

    __half* Qs = tiles + warp * 3 * ATT_TILE;
    __half* Ks = Qs + ATT_TILE;
    __half* Vs = Ks + ATT_TILE;
    const uint32_t qb = (uint32_t)__cvta_generic_to_shared(Qs);
    const uint32_t kb = (uint32_t)__cvta_generic_to_shared(Ks);
    const uint32_t vbb = (uint32_t)__cvta_generic_to_shared(Vs);

    // zero pad rows 49..63 of all three tiles (once; loads never touch them)
    for (int i = lane; i < 225; i += 32) {
        int t = i / 75, rem = i % 75;
        int row = 49 + rem / 5, ch = rem % 5;
        *(uint4*)(Qs + t * ATT_TILE + row * 40 + ch * 8) = make_uint4(0, 0, 0, 0);
    }
    __syncwarp();

    for (int hh = 0; hh < 2; hh++) {
        const int head = warp * 2 + hh;
        const __half* base = qkv + (size_t)win * NTOK * (3 * CC) + head * HD;
        for (int i = lane; i < 196; i += 32) {        // 49 rows x 4 chunks of 8 halves
            int row = i >> 2, ch = i & 3;
            const __half* rp = base + (size_t)row * (3 * CC) + ch * 8;
            *(uint4*)(Qs + row * 40 + ch * 8) = *(const uint4*)(rp);
            *(uint4*)(Ks + row * 40 + ch * 8) = *(const uint4*)(rp + CC);
            *(uint4*)(Vs + row * 40 + ch * 8) = *(const uint4*)(rp + 2 * CC);
        }
        __syncwarp();
        const float* rpb_h = rpbs + head * 172;

        #pragma unroll
        for (int pass = 0; pass < 2; pass++) {
            const int rowb = pass * 32;

            // ---- S = Q @ K^T  (32 rows x 64 cols) ----
            float sacc[2][8][4];
            #pragma unroll
            for (int mi = 0; mi < 2; mi++)
                #pragma unroll
                for (int ni = 0; ni < 8; ni++) {
                    sacc[mi][ni][0] = 0.f; sacc[mi][ni][1] = 0.f;
                    sacc[mi][ni][2] = 0.f; sacc[mi][ni][3] = 0.f;
                }
            #pragma unroll
            for (int kk = 0; kk < 2; kk++) {          // two k16 steps (HD=32)
                uint32_t qa[2][4], kf[8][2];
                #pragma unroll
                for (int mi = 0; mi < 2; mi++)
                    ldsm_x4(qa[mi][0], qa[mi][1], qa[mi][2], qa[mi][3],
                        qb + (uint32_t)((rowb + mi*16 + (sub&1)*8 + srow) * 80
                                        + ((sub>>1)*8 + kk*16) * 2));
                #pragma unroll
                for (int p = 0; p < 4; p++)
                    ldsm_x4(kf[2*p][0], kf[2*p][1], kf[2*p+1][0], kf[2*p+1][1],
                        kb + (uint32_t)((p*16 + (sub>>1)*8 + srow) * 80
                                        + ((sub&1)*8 + kk*16) * 2));
                #pragma unroll
                for (int mi = 0; mi < 2; mi++)
                    #pragma unroll
                    for (int ni = 0; ni < 8; ni++)
                        mma16816(sacc[mi][ni], qa[mi], kf[ni]);
            }

            // ---- bias (scale + rpb + mask) and softmax in fragments ----
            float rinv[2][2];
            #pragma unroll
            for (int mi = 0; mi < 2; mi++) {
                int r0 = rowb + mi * 16 + lr;
                int r1 = r0 + 8;
                int in0 = DIV7(r0), jn0 = r0 - 7 * in0, g0 = regn[r0];
                int in1 = DIV7(r1), jn1 = r1 - 7 * in1, g1 = regn[r1];
                #pragma unroll
                for (int ni = 0; ni < 8; ni++) {
                    int m0 = ni * 8 + 2 * lc;
                    int m1 = m0 + 1;
                    int im0 = DIV7(m0), jm0 = m0 - 7 * im0;
                    int im1 = DIV7(m1), jm1 = m1 - 7 * im1;
                    bool v0ok = (m0 < NTOK), v1ok = (m1 < NTOK);
                    int gm0 = v0ok ? regn[m0] : -1;
                    int gm1 = v1ok ? regn[m1] : -1;
                    int x00 = v0ok ? ((jn0 - jm0 + 6) * 13 + in0 - im0 + 6) : 0;
                    int x01 = v1ok ? ((jn0 - jm1 + 6) * 13 + in0 - im1 + 6) : 0;
                    int x10 = v0ok ? ((jn1 - jm0 + 6) * 13 + in1 - im0 + 6) : 0;
                    int x11 = v1ok ? ((jn1 - jm1 + 6) * 13 + in1 - im1 + 6) : 0;
                    sacc[mi][ni][0] = v0ok ? (sacc[mi][ni][0] * ATT_SCALE + rpb_h[x00]
                                              + ((g0 != gm0) ? -100.f : 0.f)) : -1e9f;
                    sacc[mi][ni][1] = v1ok ? (sacc[mi][ni][1] * ATT_SCALE + rpb_h[x01]
                                              + ((g0 != gm1) ? -100.f : 0.f)) : -1e9f;
                    sacc[mi][ni][2] = v0ok ? (sacc[mi][ni][2] * ATT_SCALE + rpb_h[x10]
                                              + ((g1 != gm0) ? -100.f : 0.f)) : -1e9f;
                    sacc[mi][ni][3] = v1ok ? (sacc[mi][ni][3] * ATT_SCALE + rpb_h[x11]
                                              + ((g1 != gm1) ? -100.f : 0.f)) : -1e9f;
                }
                // row max over this thread's 16 values, then across 4-lane row group
                float mx0 = -1e30f, mx1 = -1e30f;
                #pragma unroll
                for (int ni = 0; ni < 8; ni++) {
                    mx0 = fmaxf(mx0, fmaxf(sacc[mi][ni][0], sacc[mi][ni][1]));
                    mx1 = fmaxf(mx1, fmaxf(sacc[mi][ni][2], sacc[mi][ni][3]));
                }
                mx0 = fmaxf(mx0, __shfl_xor_sync(0xffffffffu, mx0, 1));
                mx0 = fmaxf(mx0, __shfl_xor_sync(0xffffffffu, mx0, 2));
                mx1 = fmaxf(mx1, __shfl_xor_sync(0xffffffffu, mx1, 1));
                mx1 = fmaxf(mx1, __shfl_xor_sync(0xffffffffu, mx1, 2));
                float s0 = 0.f, s1 = 0.f;
                #pragma unroll
                for (int ni = 0; ni < 8; ni++) {
                    float e0 = __expf(sacc[mi][ni][0] - mx0);
                    float e1 = __expf(sacc[mi][ni][1] - mx0);
                    float e2 = __expf(sacc[mi][ni][2] - mx1);
                    float e3 = __expf(sacc[mi][ni][3] - mx1);
                    sacc[mi][ni][0] = e0; sacc[mi][ni][1] = e1;
                    sacc[mi][ni][2] = e2; sacc[mi][ni][3] = e3;
                    s0 += e0 + e1; s1 += e2 + e3;
                }
                s0 += __shfl_xor_sync(0xffffffffu, s0, 1);
                s0 += __shfl_xor_sync(0xffffffffu, s0, 2);
                s1 += __shfl_xor_sync(0xffffffffu, s1, 1);
                s1 += __shfl_xor_sync(0xffffffffu, s1, 2);
                rinv[mi][0] = 1.0f / s0;
                rinv[mi][1] = 1.0f / s1;
            }

            // ---- O = P @ V  (32 rows x 32 cols) ----
            float oacc[2][4][4];
            #pragma unroll
            for (int mi = 0; mi < 2; mi++)
                #pragma unroll
                for (int ni = 0; ni < 4; ni++) {
                    oacc[mi][ni][0] = 0.f; oacc[mi][ni][1] = 0.f;
                    oacc[mi][ni][2] = 0.f; oacc[mi][ni][3] = 0.f;
                }
            #pragma unroll
            for (int kbk = 0; kbk < 4; kbk++) {        // k = 64 tokens
                uint32_t vf[4][2];
                #pragma unroll
                for (int g = 0; g < 2; g++)
                    ldsm_x4_t(vf[2*g][0], vf[2*g][1], vf[2*g+1][0], vf[2*g+1][1],
                        vbb + (uint32_t)((kbk*16 + (sub&1)*8 + srow) * 80
                                         + ((sub>>1)*8 + g*16) * 2));
                #pragma unroll
                for (int mi = 0; mi < 2; mi++) {
                    uint32_t ap[4];
                    ap[0] = packh2(sacc[mi][2*kbk][0],   sacc[mi][2*kbk][1]);
                    ap[1] = packh2(sacc[mi][2*kbk][2],   sacc[mi][2*kbk][3]);
                    ap[2] = packh2(sacc[mi][2*kbk+1][0], sacc[mi][2*kbk+1][1]);
                    ap[3] = packh2(sacc[mi][2*kbk+1][2], sacc[mi][2*kbk+1][3]);
                    #pragma unroll
                    for (int ni = 0; ni < 4; ni++)
                        mma16816(oacc[mi][ni], ap, vf[ni]);
                }
            }

            // ---- store rows < 49, normalized ----
            #pragma unroll
            for (int mi = 0; mi < 2; mi++) {
                int r0 = rowb + mi * 16 + lr;
                int r1 = r0 + 8;
                float i0 = rinv[mi][0], i1 = rinv[mi][1];
                #pragma unroll
                for (int ni = 0; ni < 4; ni++) {
                    int col = ni * 8 + 2 * lc;
                    if (r0 < NTOK)
                        *(__half2*)(o + (size_t)(win * NTOK + r0) * CC + head * HD + col)
                            = __floats2half2_rn(oacc[mi][ni][0] * i0, oacc[mi][ni][1] * i0);
                    if (r1 < NTOK)
                        *(__half2*)(o + (size_t)(win * NTOK + r1) * CC + head * HD + col)
                            = __floats2half2_rn(oacc[mi][ni][2] * i1, oacc[mi][ni][3] * i1);
                }
            }
        }
        __syncwarp();
    }
}

// ---------------- host launcher ----------------
extern "C" void kernel_launch(void* const* d_in, const int* in_sizes, int n_in,
                              void* d_out, int out_size)
{
    const float* x      = (const float*)d_in[0];
    const float* ln1_s  = (const float*)d_in[1];
    const float* ln1_b  = (const float*)d_in[2];
    const float* qkv_w  = (const float*)d_in[3];
    const float* qkv_b  = (const float*)d_in[4];
    const float* rpb    = (const float*)d_in[5];
    const float* proj_w = (const float*)d_in[6];
    const float* proj_b = (const float*)d_in[7];
    const float* ln2_s  = (const float*)d_in[8];
    const float* ln2_b  = (const float*)d_in[9];
    const float* fc1_w  = (const float*)d_in[10];
    const float* fc1_b  = (const float*)d_in[11];
    const float* fc2_w  = (const float*)d_in[12];
    const float* fc2_b  = (const float*)d_in[13];
    float* out = (float*)d_out;

    __half *ph, *pqkv, *po, *pact, *pwt;
    cudaGetSymbolAddress((void**)&ph,   g_h16);
    cudaGetSymbolAddress((void**)&pqkv, g_qkv16);
    cudaGetSymbolAddress((void**)&po,   g_o16);
    cudaGetSymbolAddress((void**)&pact, g_act16);
    cudaGetSymbolAddress((void**)&pwt,  g_wt);

    static int smem_set = 0;
    if (!smem_set) {
        cudaFuncSetAttribute(hgemm_kernel<0, true >, cudaFuncAttributeMaxDynamicSharedMemorySize, HG_SMEM);
        cudaFuncSetAttribute(hgemm_kernel<1, true >, cudaFuncAttributeMaxDynamicSharedMemorySize, HG_SMEM);
        cudaFuncSetAttribute(hgemm_kernel<2, false>, cudaFuncAttributeMaxDynamicSharedMemorySize, HG_SMEM);
        cudaFuncSetAttribute(hgemm_kernel<3, false>, cudaFuncAttributeMaxDynamicSharedMemorySize, HG_SMEM);
        cudaFuncSetAttribute(attn_mma_kernel, cudaFuncAttributeMaxDynamicSharedMemorySize, ATT_SMEM);
        smem_set = 1;
    }

    // 0. weight convert + transpose
    wconv_kernel<<<dim3(1536/32, 512/32),  dim3(32, 8)>>>(qkv_w,  pwt + WQKV_OFF,  512,  1536);
    wconv_kernel<<<dim3(512/32,  512/32),  dim3(32, 8)>>>(proj_w, pwt + WPROJ_OFF, 512,  512);
    wconv_kernel<<<dim3(2048/32, 512/32),  dim3(32, 8)>>>(fc1_w,  pwt + WFC1_OFF,  512,  2048);
    wconv_kernel<<<dim3(512/32,  2048/32), dim3(32, 8)>>>(fc2_w,  pwt + WFC2_OFF,  2048, 512);

    // 1. LN1 + shift + window partition -> fp16
    ln_kernel<true><<<TOT, 128>>>(x, ln1_s, ln1_b, ph);
    // 2. QKV GEMM
    hgemm_kernel<0, true><<<dim3(1536/128, TOT/128), 128, HG_SMEM>>>(
        ph, pwt + WQKV_OFF, qkv_b, pqkv, nullptr, TOT, 1536, 512);
    // 3. tensor-core windowed attention
    attn_mma_kernel<<<BB * NWIN, 256, ATT_SMEM>>>(pqkv, rpb, po);
    // 4. proj GEMM + fused window-reverse scatter + residual -> f32 out
    hgemm_kernel<3, false><<<dim3(512/128, TOT/128), 128, HG_SMEM>>>(
        po, pwt + WPROJ_OFF, proj_b, out, x, TOT, 512, 512);
    // 5. LN2 -> fp16
    ln_kernel<false><<<TOT, 128>>>(out, ln2_s, ln2_b, ph);
    // 6. FC1 + GELU
    hgemm_kernel<1, true><<<dim3(HID/128, TOT/128), 128, HG_SMEM>>>(
        ph, pwt + WFC1_OFF, fc1_b, pact, nullptr, TOT, HID, 512);
    // 7. FC2 + residual
    hgemm_kernel<2, false><<<dim3(512/128, TOT/128), 128, HG_SMEM>>>(
        pact, pwt + WFC2_OFF, fc2_b, out, out, TOT, 512, HID);
}

// round 12
// speedup vs baseline: 2.3105x; 1.2014x over previous
#include <cuda_runtime.h>
#include <cuda_fp16.h>
#include <math.h>
#include <stdint.h>

// ---------------- problem constants ----------------
#define HH 56
#define WW_ 56
#define CC 512
#define NHEAD 16
#define WSZ 7
#define SSH 3
#define HID 2048
#define HD 32
#define NTOK 49
#define NWH 8
#define NWW 8
#define NWIN 64
#define BB 16
#define TOT (BB*HH*WW_)   // 50176 tokens
#define LN_EPS 1e-5f
#define ATT_SCALE 0.17677669529663687f
#define DIV7(x) (((x) * 9363) >> 16)    // exact for 0..63

// ---------------- scratch (device globals, no allocs) ----------------
__device__ __align__(16) __half g_h16  [TOT * CC];
__device__ __align__(16) __half g_qkv16[TOT * 3 * CC];
__device__ __align__(16) __half g_o16  [TOT * CC];
__device__ __align__(16) __half g_act16[TOT * HID];
#define WQKV_OFF 0
#define WPROJ_OFF (512*1536)
#define WFC1_OFF  (WPROJ_OFF + 512*512)
#define WFC2_OFF  (WFC1_OFF + 512*2048)
__device__ __align__(16) __half g_wt[512*1536 + 512*512 + 512*2048 + 2048*512];

// ---------------- common helpers ----------------
__device__ __forceinline__ void cp_async16(uint32_t dst, const void* src) {
    asm volatile("cp.async.cg.shared.global [%0], [%1], 16;" :: "r"(dst), "l"(src));
}
__device__ __forceinline__ void ldsm_x4(uint32_t& r0, uint32_t& r1,
                                        uint32_t& r2, uint32_t& r3, uint32_t addr) {
    asm volatile("ldmatrix.sync.aligned.m8n8.x4.shared.b16 {%0,%1,%2,%3}, [%4];"
                 : "=r"(r0), "=r"(r1), "=r"(r2), "=r"(r3) : "r"(addr));
}
__device__ __forceinline__ void ldsm_x4_t(uint32_t& r0, uint32_t& r1,
                                          uint32_t& r2, uint32_t& r3, uint32_t addr) {
    asm volatile("ldmatrix.sync.aligned.m8n8.x4.trans.shared.b16 {%0,%1,%2,%3}, [%4];"
                 : "=r"(r0), "=r"(r1), "=r"(r2), "=r"(r3) : "r"(addr));
}
__device__ __forceinline__ void mma16816(float* c, const uint32_t* a, const uint32_t* b) {
    asm volatile(
        "mma.sync.aligned.m16n8k16.row.col.f32.f16.f16.f32 "
        "{%0,%1,%2,%3}, {%4,%5,%6,%7}, {%8,%9}, {%0,%1,%2,%3};"
        : "+f"(c[0]), "+f"(c[1]), "+f"(c[2]), "+f"(c[3])
        : "r"(a[0]), "r"(a[1]), "r"(a[2]), "r"(a[3]), "r"(b[0]), "r"(b[1]));
}
__device__ __forceinline__ uint32_t packh2(float a, float b) {
    __half2 h = __floats2half2_rn(a, b);
    return *(uint32_t*)&h;
}
__device__ __forceinline__ float gelu_exact(float x) {
    return 0.5f * x * (1.0f + erff(x * 0.70710678118654752f));
}

// ---------------- weight convert + transpose: W[K][N] f32 -> Wt[N][K] f16 ----------------
__global__ void wconv_kernel(const float* __restrict__ W, __half* __restrict__ Wt,
                             int K, int N)
{
    __shared__ float t[32][33];
    int nx = blockIdx.x * 32, ky = blockIdx.y * 32;
    int tx = threadIdx.x, ty = threadIdx.y;      // 32 x 8
    #pragma unroll
    for (int j = 0; j < 32; j += 8)
        t[ty + j][tx] = W[(size_t)(ky + ty + j) * N + nx + tx];
    __syncthreads();
    #pragma unroll
    for (int j = 0; j < 32; j += 8)
        Wt[(size_t)(nx + ty + j) * K + ky + tx] = __float2half(t[tx][ty + j]);
}

// ---------------- LayerNorm (optionally fused shift+window gather), fp16 out ----------------
template<bool GATHER>
__global__ void ln_kernel(const float* __restrict__ src,
                          const float* __restrict__ scale,
                          const float* __restrict__ bias,
                          __half* __restrict__ dst)
{
    int t = blockIdx.x;
    const float* sp;
    if (GATHER) {
        int b   = t / (NWIN * NTOK);
        int rem = t % (NWIN * NTOK);
        int win = rem / NTOK, pos = rem % NTOK;
        int wh = win / NWW, ww = win % NWW;
        int p = pos / WSZ, q = pos % WSZ;
        int row = (wh * WSZ + p + SSH) % HH;
        int col = (ww * WSZ + q + SSH) % WW_;
        sp = src + ((size_t)(b * HH + row) * WW_ + col) * CC;
    } else {
        sp = src + (size_t)t * CC;
    }
    __half* dp = dst + (size_t)t * CC;

    int tid = threadIdx.x;
    float4 v = *(const float4*)(sp + tid * 4);
    float s  = v.x + v.y + v.z + v.w;
    float s2 = v.x*v.x + v.y*v.y + v.z*v.z + v.w*v.w;

    __shared__ float red[8];
    #pragma unroll
    for (int off = 16; off > 0; off >>= 1) {
        s  += __shfl_down_sync(0xffffffffu, s,  off);
        s2 += __shfl_down_sync(0xffffffffu, s2, off);
    }
    int wid = tid >> 5, lane = tid & 31;
    if (lane == 0) { red[wid] = s; red[4 + wid] = s2; }
    __syncthreads();
    if (tid == 0) {
        float S  = red[0] + red[1] + red[2] + red[3];
        float S2 = red[4] + red[5] + red[6] + red[7];
        float mu  = S * (1.0f / CC);
        float var = S2 * (1.0f / CC) - mu * mu;
        red[0] = mu;
        red[1] = rsqrtf(var + LN_EPS);
    }
    __syncthreads();
    float mu = red[0], rs = red[1];
    float4 sc = *(const float4*)(scale + tid * 4);
    float4 bi = *(const float4*)(bias  + tid * 4);
    float ox = (v.x - mu) * rs * sc.x + bi.x;
    float oy = (v.y - mu) * rs * sc.y + bi.y;
    float oz = (v.z - mu) * rs * sc.z + bi.z;
    float ow = (v.w - mu) * rs * sc.w + bi.w;
    *(__half2*)(dp + tid * 4)     = __floats2half2_rn(ox, oy);
    *(__half2*)(dp + tid * 4 + 2) = __floats2half2_rn(oz, ow);
}

// ---------------- fp16 tensor-core GEMM ----------------
// 128x128 CTA tile, 256 threads (8 warps), warp tile 64x32, 4-stage cp.async + ldmatrix
#define HSTR 20                     // half2 words per row (16 data + 4 pad) -> 80B
#define NSTG 4
#define STG_WORDS (128 * HSTR)
#define HG_SMEM (2 * NSTG * STG_WORDS * 4)   // 81920 bytes

template<int EPI, bool OUTH>
__global__ __launch_bounds__(256, 2)
void hgemm_kernel(const __half* __restrict__ A, const __half* __restrict__ Bt,
                  const float* __restrict__ bias, void* __restrict__ Cout,
                  const float* __restrict__ res, int M, int N, int K)
{
    extern __shared__ uint32_t sh[];
    uint32_t* As = sh;
    uint32_t* Bs = sh + NSTG * STG_WORDS;

    const int bx = blockIdx.x;
    const int by = blockIdx.y;
    const int tid = threadIdx.x;                // 256
    const int wid = tid >> 5, lane = tid & 31;
    const int wm = wid & 1;                     // 2 warps in M (64 rows)
    const int wn = wid >> 1;                    // 4 warps in N (32 cols)
    const int lr = lane >> 2;
    const int lc = lane & 3;
    const int sub  = lane >> 3;
    const int srow = lane & 7;

    float acc[4][4][4];
    #pragma unroll
    for (int i = 0; i < 4; i++)
        #pragma unroll
        for (int j = 0; j < 4; j++) {
            acc[i][j][0] = 0.f; acc[i][j][1] = 0.f;
            acc[i][j][2] = 0.f; acc[i][j][3] = 0.f;
        }

    // staging: 256 threads, each stages 16 halves (2x16B) of one A row and one B row
    const int srow_g = tid >> 1;                // 0..127
    const int sch    = tid & 1;                 // 0 or 1 (which 16-half chunk)
    const __half* Ag = A  + (size_t)(by * 128 + srow_g) * K + sch * 16;
    const __half* Bg = Bt + (size_t)(bx * 128 + srow_g) * K + sch * 16;
    const int NS = K >> 5;

    int a_row_off[4], b_row_off[2];
    #pragma unroll
    for (int mi = 0; mi < 4; mi++)
        a_row_off[mi] = (wm * 64 + mi * 16 + (sub & 1) * 8 + srow) * HSTR + (sub >> 1) * 4;
    #pragma unroll
    for (int p = 0; p < 2; p++)
        b_row_off[p] = (wn * 32 + p * 16 + (sub >> 1) * 8 + srow) * HSTR + (sub & 1) * 4;

    #pragma unroll
    for (int p = 0; p < NSTG - 1; p++) {
        uint32_t ad = (uint32_t)__cvta_generic_to_shared(
            As + p * STG_WORDS + srow_g * HSTR + sch * 8);
        uint32_t bd = (uint32_t)__cvta_generic_to_shared(
            Bs + p * STG_WORDS + srow_g * HSTR + sch * 8);
        const __half* Agp = Ag + p * 32;
        const __half* Bgp = Bg + p * 32;
        cp_async16(ad,      Agp);
        cp_async16(ad + 16, Agp + 8);
        cp_async16(bd,      Bgp);
        cp_async16(bd + 16, Bgp + 8);
        asm volatile("cp.async.commit_group;");
    }

    for (int s = 0; s < NS; s++) {
        asm volatile("cp.async.wait_group %0;" :: "n"(NSTG - 2));
        __syncthreads();

        if (s + NSTG - 1 < NS) {
            int p = s + NSTG - 1;
            int buf = p & (NSTG - 1);
            uint32_t ad = (uint32_t)__cvta_generic_to_shared(
                As + buf * STG_WORDS + srow_g * HSTR + sch * 8);
            uint32_t bd = (uint32_t)__cvta_generic_to_shared(
                Bs + buf * STG_WORDS + srow_g * HSTR + sch * 8);
            const __half* Agp = Ag + p * 32;
            const __half* Bgp = Bg + p * 32;
            cp_async16(ad,      Agp);
            cp_async16(ad + 16, Agp + 8);
            cp_async16(bd,      Bgp);
            cp_async16(bd + 16, Bgp + 8);
            asm volatile("cp.async.commit_group;");
        }

        const int buf = s & (NSTG - 1);
        const uint32_t abase = (uint32_t)__cvta_generic_to_shared(As + buf * STG_WORDS);
        const uint32_t bbase = (uint32_t)__cvta_generic_to_shared(Bs + buf * STG_WORDS);

        #pragma unroll
        for (int kk2 = 0; kk2 < 16; kk2 += 8) {
            uint32_t af[4][4], bf[4][2];
            #pragma unroll
            for (int mi = 0; mi < 4; mi++)
                ldsm_x4(af[mi][0], af[mi][1], af[mi][2], af[mi][3],
                        abase + (uint32_t)((a_row_off[mi] + kk2) << 2));
            #pragma unroll
            for (int p = 0; p < 2; p++)
                ldsm_x4(bf[2*p][0], bf[2*p][1], bf[2*p+1][0], bf[2*p+1][1],
                        bbase + (uint32_t)((b_row_off[p] + kk2) << 2));
            #pragma unroll
            for (int mi = 0; mi < 4; mi++)
                #pragma unroll
                for (int ni = 0; ni < 4; ni++)
                    mma16816(acc[mi][ni], af[mi], bf[ni]);
        }
    }

    // epilogue
    const int m_base = by * 128 + wm * 64;
    const int n_base = bx * 128 + wn * 32;

    float2 bv[4];
    #pragma unroll
    for (int ni = 0; ni < 4; ni++)
        bv[ni] = *(const float2*)(bias + n_base + ni * 8 + 2 * lc);

    #pragma unroll
    for (int mi = 0; mi < 4; mi++) {
        int r0 = m_base + mi * 16 + lr;
        int r1 = r0 + 8;
        size_t orow0 = (size_t)r0, orow1 = (size_t)r1;
        if (EPI == 3) {
            int rows[2] = {r0, r1};
            size_t mapped[2];
            #pragma unroll
            for (int u = 0; u < 2; u++) {
                int t = rows[u];
                int b   = t / (NWIN * NTOK);
                int rem = t % (NWIN * NTOK);
                int win = rem / NTOK, pos = rem % NTOK;
                int wh = win >> 3, ww = win & 7;
                int p = pos / WSZ, q = pos % WSZ;
                int r = wh * WSZ + p + SSH; if (r >= HH) r -= HH;
                int c = ww * WSZ + q + SSH; if (c >= WW_) c -= WW_;
                mapped[u] = (size_t)(b * HH + r) * WW_ + c;
            }
            orow0 = mapped[0]; orow1 = mapped[1];
        }
        #pragma unroll
        for (int ni = 0; ni < 4; ni++) {
            int col = n_base + ni * 8 + 2 * lc;
            size_t off0 = orow0 * N + col;
            size_t off1 = orow1 * N + col;
            float2 v0, v1;
            v0.x = acc[mi][ni][0] + bv[ni].x;
            v0.y = acc[mi][ni][1] + bv[ni].y;
            v1.x = acc[mi][ni][2] + bv[ni].x;
            v1.y = acc[mi][ni][3] + bv[ni].y;
            if (EPI == 1) {
                v0.x = gelu_exact(v0.x); v0.y = gelu_exact(v0.y);
                v1.x = gelu_exact(v1.x); v1.y = gelu_exact(v1.y);
            }
            if (EPI == 2 || EPI == 3) {
                float2 q0 = *(const float2*)(res + off0);
                float2 q1 = *(const float2*)(res + off1);
                v0.x += q0.x; v0.y += q0.y;
                v1.x += q1.x; v1.y += q1.y;
            }
            if (OUTH) {
                __half* op = (__half*)Cout;
                *(__half2*)(op + off0) = __floats2half2_rn(v0.x, v0.y);
                *(__half2*)(op + off1) = __floats2half2_rn(v1.x, v1.y);
            } else {
                float* op = (float*)Cout;
                *(float2*)(op + off0) = v0;
                *(float2*)(op + off1) = v1;
            }
        }
    }
}

// ---------------- tensor-core windowed attention (unchanged from R10) ----------------
#define ATT_TILE 2560
#define ATT_SMEM (8*3*ATT_TILE*2 + 16*172*4 + 64*4)

__global__ __launch_bounds__(256, 1)
void attn_mma_kernel(const __half* __restrict__ qkv,
                     const float* __restrict__ rpb_table,
                     __half* __restrict__ o)
{
    extern __shared__ __half smha[];
    __half* tiles = smha;
    float*  rpbs  = (float*)(smha + 8*3*ATT_TILE);
    int*    regn  = (int*)(rpbs + 16*172);

    const int win = blockIdx.x;
    const int wloc = win & 63;
    const int wh = wloc >> 3, ww = wloc & 7;
    const int tid = threadIdx.x;
    const int warp = tid >> 5, lane = tid & 31;
    const int lr = lane >> 2, lc = lane & 3;
    const int sub = lane >> 3, srow = lane & 7;

    for (int i = tid; i < 16 * 172; i += 256) {
        int h = i / 172, r = i % 172;
        rpbs[i] = (r < 169) ? rpb_table[r * 16 + h] : 0.0f;
    }
    if (tid < 64) {
        int p = DIV7(tid), q = tid - 7 * p;
        int r = wh * 7 + p, c = ww * 7 + q;
        int rr = (r < 49) ? 0 : ((r < 53) ? 1 : 2);
        int rc = (c < 49) ? 0 : ((c < 53) ? 1 : 2);
        regn[tid] = rr * 3 + rc;
    }
    __syncthreads();

    __half* Qs = tiles + warp * 3 * ATT_TILE;
    __half* Ks = Qs + ATT_TILE;
    __half* Vs = Ks + ATT_TILE;
    const uint32_t qb = (uint32_t)__cvta_generic_to_shared(Qs);
    const uint32_t kb = (uint32_t)__cvta_generic_to_shared(Ks);
    const uint32_t vbb = (uint32_t)__cvta_generic_to_shared(Vs);

    for (int i = lane; i < 225; i += 32) {
        int t = i / 75, rem = i % 75;
        int row = 49 + rem / 5, ch = rem % 5;
        *(uint4*)(Qs + t * ATT_TILE + row * 40 + ch * 8) = make_uint4(0, 0, 0, 0);
    }
    __syncwarp();

    for (int hh = 0; hh < 2; hh++) {
        const int head = warp * 2 + hh;
        const __half* base = qkv + (size_t)win * NTOK * (3 * CC) + head * HD;
        for (int i = lane; i < 196; i += 32) {
            int row = i >> 2, ch = i & 3;
            const __half* rp = base + (size_t)row * (3 * CC) + ch * 8;
            *(uint4*)(Qs + row * 40 + ch * 8) = *(const uint4*)(rp);
            *(uint4*)(Ks + row * 40 + ch * 8) = *(const uint4*)(rp + CC);
            *(uint4*)(Vs + row * 40 + ch * 8) = *(const uint4*)(rp + 2 * CC);
        }
        __syncwarp();
        const float* rpb_h = rpbs + head * 172;

        #pragma unroll
        for (int pass = 0; pass < 2; pass++) {
            const int rowb = pass * 32;

            float sacc[2][8][4];
            #pragma unroll
            for (int mi = 0; mi < 2; mi++)
                #pragma unroll
                for (int ni = 0; ni < 8; ni++) {
                    sacc[mi][ni][0] = 0.f; sacc[mi][ni][1] = 0.f;
                    sacc[mi][ni][2] = 0.f; sacc[mi][ni][3] = 0.f;
                }
            #pragma unroll
            for (int kk = 0; kk < 2; kk++) {
                uint32_t qa[2][4], kf[8][2];
                #pragma unroll
                for (int mi = 0; mi < 2; mi++)
                    ldsm_x4(qa[mi][0], qa[mi][1], qa[mi][2], qa[mi][3],
                        qb + (uint32_t)((rowb + mi*16 + (sub&1)*8 + srow) * 80
                                        + ((sub>>1)*8 + kk*16) * 2));
                #pragma unroll
                for (int p = 0; p < 4; p++)
                    ldsm_x4(kf[2*p][0], kf[2*p][1], kf[2*p+1][0], kf[2*p+1][1],
                        kb + (uint32_t)((p*16 + (sub>>1)*8 + srow) * 80
                                        + ((sub&1)*8 + kk*16) * 2));
                #pragma unroll
                for (int mi = 0; mi < 2; mi++)
                    #pragma unroll
                    for (int ni = 0; ni < 8; ni++)
                        mma16816(sacc[mi][ni], qa[mi], kf[ni]);
            }

            float rinv[2][2];
            #pragma unroll
            for (int mi = 0; mi < 2; mi++) {
                int r0 = rowb + mi * 16 + lr;
                int r1 = r0 + 8;
                int in0 = DIV7(r0), jn0 = r0 - 7 * in0, g0 = regn[r0];
                int in1 = DIV7(r1), jn1 = r1 - 7 * in1, g1 = regn[r1];
                #pragma unroll
                for (int ni = 0; ni < 8; ni++) {
                    int m0 = ni * 8 + 2 * lc;
                    int m1 = m0 + 1;
                    int im0 = DIV7(m0), jm0 = m0 - 7 * im0;
                    int im1 = DIV7(m1), jm1 = m1 - 7 * im1;
                    bool v0ok = (m0 < NTOK), v1ok = (m1 < NTOK);
                    int gm0 = v0ok ? regn[m0] : -1;
                    int gm1 = v1ok ? regn[m1] : -1;
                    int x00 = v0ok ? ((jn0 - jm0 + 6) * 13 + in0 - im0 + 6) : 0;
                    int x01 = v1ok ? ((jn0 - jm1 + 6) * 13 + in0 - im1 + 6) : 0;
                    int x10 = v0ok ? ((jn1 - jm0 + 6) * 13 + in1 - im0 + 6) : 0;
                    int x11 = v1ok ? ((jn1 - jm1 + 6) * 13 + in1 - im1 + 6) : 0;
                    sacc[mi][ni][0] = v0ok ? (sacc[mi][ni][0] * ATT_SCALE + rpb_h[x00]
                                              + ((g0 != gm0) ? -100.f : 0.f)) : -1e9f;
                    sacc[mi][ni][1] = v1ok ? (sacc[mi][ni][1] * ATT_SCALE + rpb_h[x01]
                                              + ((g0 != gm1) ? -100.f : 0.f)) : -1e9f;
                    sacc[mi][ni][2] = v0ok ? (sacc[mi][ni][2] * ATT_SCALE + rpb_h[x10]
                                              + ((g1 != gm0) ? -100.f : 0.f)) : -1e9f;
                    sacc[mi][ni][3] = v1ok ? (sacc[mi][ni][3] * ATT_SCALE + rpb_h[x11]
                                              + ((g1 != gm1) ? -100.f : 0.f)) : -1e9f;
                }
                float mx0 = -1e30f, mx1 = -1e30f;
                #pragma unroll
                for (int ni = 0; ni < 8; ni++) {
                    mx0 = fmaxf(mx0, fmaxf(sacc[mi][ni][0], sacc[mi][ni][1]));
                    mx1 = fmaxf(mx1, fmaxf(sacc[mi][ni][2], sacc[mi][ni][3]));
                }
                mx0 = fmaxf(mx0, __shfl_xor_sync(0xffffffffu, mx0, 1));
                mx0 = fmaxf(mx0, __shfl_xor_sync(0xffffffffu, mx0, 2));
                mx1 = fmaxf(mx1, __shfl_xor_sync(0xffffffffu, mx1, 1));
                mx1 = fmaxf(mx1, __shfl_xor_sync(0xffffffffu, mx1, 2));
                float s0 = 0.f, s1 = 0.f;
                #pragma unroll
                for (int ni = 0; ni < 8; ni++) {
                    float e0 = __expf(sacc[mi][ni][0] - mx0);
                    float e1 = __expf(sacc[mi][ni][1] - mx0);
                    float e2 = __expf(sacc[mi][ni][2] - mx1);
                    float e3 = __expf(sacc[mi][ni][3] - mx1);
                    sacc[mi][ni][0] = e0; sacc[mi][ni][1] = e1;
                    sacc[mi][ni][2] = e2; sacc[mi][ni][3] = e3;
                    s0 += e0 + e1; s1 += e2 + e3;
                }
                s0 += __shfl_xor_sync(0xffffffffu, s0, 1);
                s0 += __shfl_xor_sync(0xffffffffu, s0, 2);
                s1 += __shfl_xor_sync(0xffffffffu, s1, 1);
                s1 += __shfl_xor_sync(0xffffffffu, s1, 2);
                rinv[mi][0] = 1.0f / s0;
                rinv[mi][1] = 1.0f / s1;
            }

            float oacc[2][4][4];
            #pragma unroll
            for (int mi = 0; mi < 2; mi++)
                #pragma unroll
                for (int ni = 0; ni < 4; ni++) {
                    oacc[mi][ni][0] = 0.f; oacc[mi][ni][1] = 0.f;
                    oacc[mi][ni][2] = 0.f; oacc[mi][ni][3] = 0.f;
                }
            #pragma unroll
            for (int kbk = 0; kbk < 4; kbk++) {
                uint32_t vf[4][2];
                #pragma unroll
                for (int g = 0; g < 2; g++)
                    ldsm_x4_t(vf[2*g][0], vf[2*g][1], vf[2*g+1][0], vf[2*g+1][1],
                        vbb + (uint32_t)((kbk*16 + (sub&1)*8 + srow) * 80
                                         + ((sub>>1)*8 + g*16) * 2));
                #pragma unroll
                for (int mi = 0; mi < 2; mi++) {
                    uint32_t ap[4];
                    ap[0] = packh2(sacc[mi][2*kbk][0],   sacc[mi][2*kbk][1]);
                    ap[1] = packh2(sacc[mi][2*kbk][2],   sacc[mi][2*kbk][3]);
                    ap[2] = packh2(sacc[mi][2*kbk+1][0], sacc[mi][2*kbk+1][1]);
                    ap[3] = packh2(sacc[mi][2*kbk+1][2], sacc[mi][2*kbk+1][3]);
                    #pragma unroll
                    for (int ni = 0; ni < 4; ni++)
                        mma16816(oacc[mi][ni], ap, vf[ni]);
                }
            }

            #pragma unroll
            for (int mi = 0; mi < 2; mi++) {
                int r0 = rowb + mi * 16 + lr;
                int r1 = r0 + 8;
                float i0 = rinv[mi][0], i1 = rinv[mi][1];
                #pragma unroll
                for (int ni = 0; ni < 4; ni++) {
                    int col = ni * 8 + 2 * lc;
                    if (r0 < NTOK)
                        *(__half2*)(o + (size_t)(win * NTOK + r0) * CC + head * HD + col)
                            = __floats2half2_rn(oacc[mi][ni][0] * i0, oacc[mi][ni][1] * i0);
                    if (r1 < NTOK)
                        *(__half2*)(o + (size_t)(win * NTOK + r1) * CC + head * HD + col)
                            = __floats2half2_rn(oacc[mi][ni][2] * i1, oacc[mi][ni][3] * i1);
                }
            }
        }
        __syncwarp();
    }
}

// ---------------- host launcher ----------------
extern "C" void kernel_launch(void* const* d_in, const int* in_sizes, int n_in,
                              void* d_out, int out_size)
{
    const float* x      = (const float*)d_in[0];
    const float* ln1_s  = (const float*)d_in[1];
    const float* ln1_b  = (const float*)d_in[2];
    const float* qkv_w  = (const float*)d_in[3];
    const float* qkv_b  = (const float*)d_in[4];
    const float* rpb    = (const float*)d_in[5];
    const float* proj_w = (const float*)d_in[6];
    const float* proj_b = (const float*)d_in[7];
    const float* ln2_s  = (const float*)d_in[8];
    const float* ln2_b  = (const float*)d_in[9];
    const float* fc1_w  = (const float*)d_in[10];
    const float* fc1_b  = (const float*)d_in[11];
    const float* fc2_w  = (const float*)d_in[12];
    const float* fc2_b  = (const float*)d_in[13];
    float* out = (float*)d_out;

    __half *ph, *pqkv, *po, *pact, *pwt;
    cudaGetSymbolAddress((void**)&ph,   g_h16);
    cudaGetSymbolAddress((void**)&pqkv, g_qkv16);
    cudaGetSymbolAddress((void**)&po,   g_o16);
    cudaGetSymbolAddress((void**)&pact, g_act16);
    cudaGetSymbolAddress((void**)&pwt,  g_wt);

    static int smem_set = 0;
    if (!smem_set) {
        cudaFuncSetAttribute(hgemm_kernel<0, true >, cudaFuncAttributeMaxDynamicSharedMemorySize, HG_SMEM);
        cudaFuncSetAttribute(hgemm_kernel<1, true >, cudaFuncAttributeMaxDynamicSharedMemorySize, HG_SMEM);
        cudaFuncSetAttribute(hgemm_kernel<2, false>, cudaFuncAttributeMaxDynamicSharedMemorySize, HG_SMEM);
        cudaFuncSetAttribute(hgemm_kernel<3, false>, cudaFuncAttributeMaxDynamicSharedMemorySize, HG_SMEM);
        cudaFuncSetAttribute(attn_mma_kernel, cudaFuncAttributeMaxDynamicSharedMemorySize, ATT_SMEM);
        smem_set = 1;
    }

    // 0. weight convert + transpose
    wconv_kernel<<<dim3(1536/32, 512/32),  dim3(32, 8)>>>(qkv_w,  pwt + WQKV_OFF,  512,  1536);
    wconv_kernel<<<dim3(512/32,  512/32),  dim3(32, 8)>>>(proj_w, pwt + WPROJ_OFF, 512,  512);
    wconv_kernel<<<dim3(2048/32, 512/32),  dim3(32, 8)>>>(fc1_w,  pwt + WFC1_OFF,  512,  2048);
    wconv_kernel<<<dim3(512/32,  2048/32), dim3(32, 8)>>>(fc2_w,  pwt + WFC2_OFF,  2048, 512);

    // 1. LN1 + shift + window partition -> fp16
    ln_kernel<true><<<TOT, 128>>>(x, ln1_s, ln1_b, ph);
    // 2. QKV GEMM
    hgemm_kernel<0, true><<<dim3(1536/128, TOT/128), 256, HG_SMEM>>>(
        ph, pwt + WQKV_OFF, qkv_b, pqkv, nullptr, TOT, 1536, 512);
    // 3. tensor-core windowed attention
    attn_mma_kernel<<<BB * NWIN, 256, ATT_SMEM>>>(pqkv, rpb, po);
    // 4. proj GEMM + fused window-reverse scatter + residual -> f32 out
    hgemm_kernel<3, false><<<dim3(512/128, TOT/128), 256, HG_SMEM>>>(
        po, pwt + WPROJ_OFF, proj_b, out, x, TOT, 512, 512);
    // 5. LN2 -> fp16
    ln_kernel<false><<<TOT, 128>>>(out, ln2_s, ln2_b, ph);
    // 6. FC1 + GELU
    hgemm_kernel<1, true><<<dim3(HID/128, TOT/128), 256, HG_SMEM>>>(
        ph, pwt + WFC1_OFF, fc1_b, pact, nullptr, TOT, HID, 512);
    // 7. FC2 + residual
    hgemm_kernel<2, false><<<dim3(512/128, TOT/128), 256, HG_SMEM>>>(
        pact, pwt + WFC2_OFF, fc2_b, out, out, TOT, 512, HID);
}

// round 13
// speedup vs baseline: 2.3420x; 1.0137x over previous
#include <cuda_runtime.h>
#include <cuda_fp16.h>
#include <math.h>
#include <stdint.h>

// ---------------- problem constants ----------------
#define HH 56
#define WW_ 56
#define CC 512
#define NHEAD 16
#define WSZ 7
#define SSH 3
#define HID 2048
#define HD 32
#define NTOK 49
#define NWH 8
#define NWW 8
#define NWIN 64
#define BB 16
#define TOT (BB*HH*WW_)   // 50176 tokens
#define LN_EPS 1e-5f
#define ATT_SCALE 0.17677669529663687f
#define DIV7(x) (((x) * 9363) >> 16)    // exact for 0..63

// ---------------- scratch (device globals, no allocs) ----------------
__device__ __align__(16) __half g_h16  [TOT * CC];
__device__ __align__(16) __half g_qkv16[TOT * 3 * CC];
__device__ __align__(16) __half g_o16  [TOT * CC];
__device__ __align__(16) __half g_act16[TOT * HID];
#define WQKV_OFF 0
#define WPROJ_OFF (512*1536)
#define WFC1_OFF  (WPROJ_OFF + 512*512)
#define WFC2_OFF  (WFC1_OFF + 512*2048)
__device__ __align__(16) __half g_wt[512*1536 + 512*512 + 512*2048 + 2048*512];

// ---------------- common helpers ----------------
__device__ __forceinline__ void cp_async16(uint32_t dst, const void* src) {
    asm volatile("cp.async.cg.shared.global [%0], [%1], 16;" :: "r"(dst), "l"(src));
}
__device__ __forceinline__ void ldsm_x4(uint32_t& r0, uint32_t& r1,
                                        uint32_t& r2, uint32_t& r3, uint32_t addr) {
    asm volatile("ldmatrix.sync.aligned.m8n8.x4.shared.b16 {%0,%1,%2,%3}, [%4];"
                 : "=r"(r0), "=r"(r1), "=r"(r2), "=r"(r3) : "r"(addr));
}
__device__ __forceinline__ void ldsm_x4_t(uint32_t& r0, uint32_t& r1,
                                          uint32_t& r2, uint32_t& r3, uint32_t addr) {
    asm volatile("ldmatrix.sync.aligned.m8n8.x4.trans.shared.b16 {%0,%1,%2,%3}, [%4];"
                 : "=r"(r0), "=r"(r1), "=r"(r2), "=r"(r3) : "r"(addr));
}
__device__ __forceinline__ void mma16816(float* c, const uint32_t* a, const uint32_t* b) {
    asm volatile(
        "mma.sync.aligned.m16n8k16.row.col.f32.f16.f16.f32 "
        "{%0,%1,%2,%3}, {%4,%5,%6,%7}, {%8,%9}, {%0,%1,%2,%3};"
        : "+f"(c[0]), "+f"(c[1]), "+f"(c[2]), "+f"(c[3])
        : "r"(a[0]), "r"(a[1]), "r"(a[2]), "r"(a[3]), "r"(b[0]), "r"(b[1]));
}
__device__ __forceinline__ uint32_t packh2(float a, float b) {
    __half2 h = __floats2half2_rn(a, b);
    return *(uint32_t*)&h;
}
__device__ __forceinline__ float gelu_exact(float x) {
    return 0.5f * x * (1.0f + erff(x * 0.70710678118654752f));
}

// ---------------- combined weight convert+transpose: 4 segments in one launch ----------------
// seg tiles: qkv 48x16=768, proj 16x16=256, fc1 64x16=1024, fc2 16x64=1024 -> 3072 blocks
__global__ void wconv_all_kernel(const float* __restrict__ W0, const float* __restrict__ W1,
                                 const float* __restrict__ W2, const float* __restrict__ W3,
                                 __half* __restrict__ wt)
{
    __shared__ float t[32][33];
    int b = blockIdx.x;
    const float* W; __half* Wt; int K, N, ntx, local;
    if (b < 768)       { W = W0; Wt = wt + WQKV_OFF;  K = 512;  N = 1536; ntx = 48; local = b; }
    else if (b < 1024) { W = W1; Wt = wt + WPROJ_OFF; K = 512;  N = 512;  ntx = 16; local = b - 768; }
    else if (b < 2048) { W = W2; Wt = wt + WFC1_OFF;  K = 512;  N = 2048; ntx = 64; local = b - 1024; }
    else               { W = W3; Wt = wt + WFC2_OFF;  K = 2048; N = 512;  ntx = 16; local = b - 2048; }
    int nx = (local % ntx) * 32, ky = (local / ntx) * 32;
    int tx = threadIdx.x, ty = threadIdx.y;      // 32 x 8
    #pragma unroll
    for (int j = 0; j < 32; j += 8)
        t[ty + j][tx] = W[(size_t)(ky + ty + j) * N + nx + tx];
    __syncthreads();
    #pragma unroll
    for (int j = 0; j < 32; j += 8)
        Wt[(size_t)(nx + ty + j) * K + ky + tx] = __float2half(t[tx][ty + j]);
}

// ---------------- LayerNorm, warp-per-row (8 rows/block, no block barriers) ----------------
template<bool GATHER>
__global__ __launch_bounds__(256)
void ln_kernel(const float* __restrict__ src,
               const float* __restrict__ scale,
               const float* __restrict__ bias,
               __half* __restrict__ dst)
{
    const int warp = threadIdx.x >> 5, lane = threadIdx.x & 31;
    const int t = blockIdx.x * 8 + warp;
    const float* sp;
    if (GATHER) {
        int b   = t / (NWIN * NTOK);
        int rem = t % (NWIN * NTOK);
        int win = rem / NTOK, pos = rem % NTOK;
        int wh = win / NWW, ww = win % NWW;
        int p = pos / WSZ, q = pos % WSZ;
        int row = (wh * WSZ + p + SSH) % HH;
        int col = (ww * WSZ + q + SSH) % WW_;
        sp = src + ((size_t)(b * HH + row) * WW_ + col) * CC;
    } else {
        sp = src + (size_t)t * CC;
    }
    __half* dp = dst + (size_t)t * CC;

    float4 v[4];
    float s = 0.f, s2 = 0.f;
    #pragma unroll
    for (int c = 0; c < 4; c++) {
        v[c] = *(const float4*)(sp + c * 128 + lane * 4);
        s  += v[c].x + v[c].y + v[c].z + v[c].w;
        s2 += v[c].x*v[c].x + v[c].y*v[c].y + v[c].z*v[c].z + v[c].w*v[c].w;
    }
    #pragma unroll
    for (int off = 16; off > 0; off >>= 1) {
        s  += __shfl_xor_sync(0xffffffffu, s,  off);
        s2 += __shfl_xor_sync(0xffffffffu, s2, off);
    }
    float mu = s * (1.0f / CC);
    float rs = rsqrtf(s2 * (1.0f / CC) - mu * mu + LN_EPS);

    #pragma unroll
    for (int c = 0; c < 4; c++) {
        int col = c * 128 + lane * 4;
        float4 sc = *(const float4*)(scale + col);
        float4 bi = *(const float4*)(bias  + col);
        float ox = (v[c].x - mu) * rs * sc.x + bi.x;
        float oy = (v[c].y - mu) * rs * sc.y + bi.y;
        float oz = (v[c].z - mu) * rs * sc.z + bi.z;
        float ow = (v[c].w - mu) * rs * sc.w + bi.w;
        uint2 o;
        o.x = packh2(ox, oy);
        o.y = packh2(oz, ow);
        *(uint2*)(dp + col) = o;
    }
}

// ---------------- fp16 tensor-core GEMM (unchanged from R11 winner) ----------------
#define HSTR 20
#define NSTG 4
#define STG_WORDS (128 * HSTR)
#define HG_SMEM (2 * NSTG * STG_WORDS * 4)   // 81920 bytes

template<int EPI, bool OUTH>
__global__ __launch_bounds__(256, 2)
void hgemm_kernel(const __half* __restrict__ A, const __half* __restrict__ Bt,
                  const float* __restrict__ bias, void* __restrict__ Cout,
                  const float* __restrict__ res, int M, int N, int K)
{
    extern __shared__ uint32_t sh[];
    uint32_t* As = sh;
    uint32_t* Bs = sh + NSTG * STG_WORDS;

    const int bx = blockIdx.x;
    const int by = blockIdx.y;
    const int tid = threadIdx.x;
    const int wid = tid >> 5, lane = tid & 31;
    const int wm = wid & 1;
    const int wn = wid >> 1;
    const int lr = lane >> 2;
    const int lc = lane & 3;
    const int sub  = lane >> 3;
    const int srow = lane & 7;

    float acc[4][4][4];
    #pragma unroll
    for (int i = 0; i < 4; i++)
        #pragma unroll
        for (int j = 0; j < 4; j++) {
            acc[i][j][0] = 0.f; acc[i][j][1] = 0.f;
            acc[i][j][2] = 0.f; acc[i][j][3] = 0.f;
        }

    const int srow_g = tid >> 1;
    const int sch    = tid & 1;
    const __half* Ag = A  + (size_t)(by * 128 + srow_g) * K + sch * 16;
    const __half* Bg = Bt + (size_t)(bx * 128 + srow_g) * K + sch * 16;
    const int NS = K >> 5;

    int a_row_off[4], b_row_off[2];
    #pragma unroll
    for (int mi = 0; mi < 4; mi++)
        a_row_off[mi] = (wm * 64 + mi * 16 + (sub & 1) * 8 + srow) * HSTR + (sub >> 1) * 4;
    #pragma unroll
    for (int p = 0; p < 2; p++)
        b_row_off[p] = (wn * 32 + p * 16 + (sub >> 1) * 8 + srow) * HSTR + (sub & 1) * 4;

    #pragma unroll
    for (int p = 0; p < NSTG - 1; p++) {
        uint32_t ad = (uint32_t)__cvta_generic_to_shared(
            As + p * STG_WORDS + srow_g * HSTR + sch * 8);
        uint32_t bd = (uint32_t)__cvta_generic_to_shared(
            Bs + p * STG_WORDS + srow_g * HSTR + sch * 8);
        const __half* Agp = Ag + p * 32;
        const __half* Bgp = Bg + p * 32;
        cp_async16(ad,      Agp);
        cp_async16(ad + 16, Agp + 8);
        cp_async16(bd,      Bgp);
        cp_async16(bd + 16, Bgp + 8);
        asm volatile("cp.async.commit_group;");
    }

    for (int s = 0; s < NS; s++) {
        asm volatile("cp.async.wait_group %0;" :: "n"(NSTG - 2));
        __syncthreads();

        if (s + NSTG - 1 < NS) {
            int p = s + NSTG - 1;
            int buf = p & (NSTG - 1);
            uint32_t ad = (uint32_t)__cvta_generic_to_shared(
                As + buf * STG_WORDS + srow_g * HSTR + sch * 8);
            uint32_t bd = (uint32_t)__cvta_generic_to_shared(
                Bs + buf * STG_WORDS + srow_g * HSTR + sch * 8);
            const __half* Agp = Ag + p * 32;
            const __half* Bgp = Bg + p * 32;
            cp_async16(ad,      Agp);
            cp_async16(ad + 16, Agp + 8);
            cp_async16(bd,      Bgp);
            cp_async16(bd + 16, Bgp + 8);
            asm volatile("cp.async.commit_group;");
        }

        const int buf = s & (NSTG - 1);
        const uint32_t abase = (uint32_t)__cvta_generic_to_shared(As + buf * STG_WORDS);
        const uint32_t bbase = (uint32_t)__cvta_generic_to_shared(Bs + buf * STG_WORDS);

        #pragma unroll
        for (int kk2 = 0; kk2 < 16; kk2 += 8) {
            uint32_t af[4][4], bf[4][2];
            #pragma unroll
            for (int mi = 0; mi < 4; mi++)
                ldsm_x4(af[mi][0], af[mi][1], af[mi][2], af[mi][3],
                        abase + (uint32_t)((a_row_off[mi] + kk2) << 2));
            #pragma unroll
            for (int p = 0; p < 2; p++)
                ldsm_x4(bf[2*p][0], bf[2*p][1], bf[2*p+1][0], bf[2*p+1][1],
                        bbase + (uint32_t)((b_row_off[p] + kk2) << 2));
            #pragma unroll
            for (int mi = 0; mi < 4; mi++)
                #pragma unroll
                for (int ni = 0; ni < 4; ni++)
                    mma16816(acc[mi][ni], af[mi], bf[ni]);
        }
    }

    const int m_base = by * 128 + wm * 64;
    const int n_base = bx * 128 + wn * 32;

    float2 bv[4];
    #pragma unroll
    for (int ni = 0; ni < 4; ni++)
        bv[ni] = *(const float2*)(bias + n_base + ni * 8 + 2 * lc);

    #pragma unroll
    for (int mi = 0; mi < 4; mi++) {
        int r0 = m_base + mi * 16 + lr;
        int r1 = r0 + 8;
        size_t orow0 = (size_t)r0, orow1 = (size_t)r1;
        if (EPI == 3) {
            int rows[2] = {r0, r1};
            size_t mapped[2];
            #pragma unroll
            for (int u = 0; u < 2; u++) {
                int t = rows[u];
                int b   = t / (NWIN * NTOK);
                int rem = t % (NWIN * NTOK);
                int win = rem / NTOK, pos = rem % NTOK;
                int wh = win >> 3, ww = win & 7;
                int p = pos / WSZ, q = pos % WSZ;
                int r = wh * WSZ + p + SSH; if (r >= HH) r -= HH;
                int c = ww * WSZ + q + SSH; if (c >= WW_) c -= WW_;
                mapped[u] = (size_t)(b * HH + r) * WW_ + c;
            }
            orow0 = mapped[0]; orow1 = mapped[1];
        }
        #pragma unroll
        for (int ni = 0; ni < 4; ni++) {
            int col = n_base + ni * 8 + 2 * lc;
            size_t off0 = orow0 * N + col;
            size_t off1 = orow1 * N + col;
            float2 v0, v1;
            v0.x = acc[mi][ni][0] + bv[ni].x;
            v0.y = acc[mi][ni][1] + bv[ni].y;
            v1.x = acc[mi][ni][2] + bv[ni].x;
            v1.y = acc[mi][ni][3] + bv[ni].y;
            if (EPI == 1) {
                v0.x = gelu_exact(v0.x); v0.y = gelu_exact(v0.y);
                v1.x = gelu_exact(v1.x); v1.y = gelu_exact(v1.y);
            }
            if (EPI == 2 || EPI == 3) {
                float2 q0 = *(const float2*)(res + off0);
                float2 q1 = *(const float2*)(res + off1);
                v0.x += q0.x; v0.y += q0.y;
                v1.x += q1.x; v1.y += q1.y;
            }
            if (OUTH) {
                __half* op = (__half*)Cout;
                *(__half2*)(op + off0) = __floats2half2_rn(v0.x, v0.y);
                *(__half2*)(op + off1) = __floats2half2_rn(v1.x, v1.y);
            } else {
                float* op = (float*)Cout;
                *(float2*)(op + off0) = v0;
                *(float2*)(op + off1) = v1;
            }
        }
    }
}

// ---------------- tensor-core windowed attention (unchanged) ----------------
#define ATT_TILE 2560
#define ATT_SMEM (8*3*ATT_TILE*2 + 16*172*4 + 64*4)

__global__ __launch_bounds__(256, 1)
void attn_mma_kernel(const __half* __restrict__ qkv,
                     const float* __restrict__ rpb_table,
                     __half* __restrict__ o)
{
    extern __shared__ __half smha[];
    __half* tiles = smha;
    float*  rpbs  = (float*)(smha + 8*3*ATT_TILE);
    int*    regn  = (int*)(rpbs + 16*172);

    const int win = blockIdx.x;
    const int wloc = win & 63;
    const int wh = wloc >> 3, ww = wloc & 7;
    const int tid = threadIdx.x;
    const int warp = tid >> 5, lane = tid & 31;
    const int lr = lane >> 2, lc = lane & 3;
    const int sub = lane >> 3, srow = lane & 7;

    for (int i = tid; i < 16 * 172; i += 256) {
        int h = i / 172, r = i % 172;
        rpbs[i] = (r < 169) ? rpb_table[r * 16 + h] : 0.0f;
    }
    if (tid < 64) {
        int p = DIV7(tid), q = tid - 7 * p;
        int r = wh * 7 + p, c = ww * 7 + q;
        int rr = (r < 49) ? 0 : ((r < 53) ? 1 : 2);
        int rc = (c < 49) ? 0 : ((c < 53) ? 1 : 2);
        regn[tid] = rr * 3 + rc;
    }
    __syncthreads();

    __half* Qs = tiles + warp * 3 * ATT_TILE;
    __half* Ks = Qs + ATT_TILE;
    __half* Vs = Ks + ATT_TILE;
    const uint32_t qb = (uint32_t)__cvta_generic_to_shared(Qs);
    const uint32_t kb = (uint32_t)__cvta_generic_to_shared(Ks);
    const uint32_t vbb = (uint32_t)__cvta_generic_to_shared(Vs);

    for (int i = lane; i < 225; i += 32) {
        int t = i / 75, rem = i % 75;
        int row = 49 + rem / 5, ch = rem % 5;
        *(uint4*)(Qs + t * ATT_TILE + row * 40 + ch * 8) = make_uint4(0, 0, 0, 0);
    }
    __syncwarp();

    for (int hh = 0; hh < 2; hh++) {
        const int head = warp * 2 + hh;
        const __half* base = qkv + (size_t)win * NTOK * (3 * CC) + head * HD;
        for (int i = lane; i < 196; i += 32) {
            int row = i >> 2, ch = i & 3;
            const __half* rp = base + (size_t)row * (3 * CC) + ch * 8;
            *(uint4*)(Qs + row * 40 + ch * 8) = *(const uint4*)(rp);
            *(uint4*)(Ks + row * 40 + ch * 8) = *(const uint4*)(rp + CC);
            *(uint4*)(Vs + row * 40 + ch * 8) = *(const uint4*)(rp + 2 * CC);
        }
        __syncwarp();
        const float* rpb_h = rpbs + head * 172;

        #pragma unroll
        for (int pass = 0; pass < 2; pass++) {
            const int rowb = pass * 32;

            float sacc[2][8][4];
            #pragma unroll
            for (int mi = 0; mi < 2; mi++)
                #pragma unroll
                for (int ni = 0; ni < 8; ni++) {
                    sacc[mi][ni][0] = 0.f; sacc[mi][ni][1] = 0.f;
                    sacc[mi][ni][2] = 0.f; sacc[mi][ni][3] = 0.f;
                }
            #pragma unroll
            for (int kk = 0; kk < 2; kk++) {
                uint32_t qa[2][4], kf[8][2];
                #pragma unroll
                for (int mi = 0; mi < 2; mi++)
                    ldsm_x4(qa[mi][0], qa[mi][1], qa[mi][2], qa[mi][3],
                        qb + (uint32_t)((rowb + mi*16 + (sub&1)*8 + srow) * 80
                                        + ((sub>>1)*8 + kk*16) * 2));
                #pragma unroll
                for (int p = 0; p < 4; p++)
                    ldsm_x4(kf[2*p][0], kf[2*p][1], kf[2*p+1][0], kf[2*p+1][1],
                        kb + (uint32_t)((p*16 + (sub>>1)*8 + srow) * 80
                                        + ((sub&1)*8 + kk*16) * 2));
                #pragma unroll
                for (int mi = 0; mi < 2; mi++)
                    #pragma unroll
                    for (int ni = 0; ni < 8; ni++)
                        mma16816(sacc[mi][ni], qa[mi], kf[ni]);
            }

            float rinv[2][2];
            #pragma unroll
            for (int mi = 0; mi < 2; mi++) {
                int r0 = rowb + mi * 16 + lr;
                int r1 = r0 + 8;
                int in0 = DIV7(r0), jn0 = r0 - 7 * in0, g0 = regn[r0];
                int in1 = DIV7(r1), jn1 = r1 - 7 * in1, g1 = regn[r1];
                #pragma unroll
                for (int ni = 0; ni < 8; ni++) {
                    int m0 = ni * 8 + 2 * lc;
                    int m1 = m0 + 1;
                    int im0 = DIV7(m0), jm0 = m0 - 7 * im0;
                    int im1 = DIV7(m1), jm1 = m1 - 7 * im1;
                    bool v0ok = (m0 < NTOK), v1ok = (m1 < NTOK);
                    int gm0 = v0ok ? regn[m0] : -1;
                    int gm1 = v1ok ? regn[m1] : -1;
                    int x00 = v0ok ? ((jn0 - jm0 + 6) * 13 + in0 - im0 + 6) : 0;
                    int x01 = v1ok ? ((jn0 - jm1 + 6) * 13 + in0 - im1 + 6) : 0;
                    int x10 = v0ok ? ((jn1 - jm0 + 6) * 13 + in1 - im0 + 6) : 0;
                    int x11 = v1ok ? ((jn1 - jm1 + 6) * 13 + in1 - im1 + 6) : 0;
                    sacc[mi][ni][0] = v0ok ? (sacc[mi][ni][0] * ATT_SCALE + rpb_h[x00]
                                              + ((g0 != gm0) ? -100.f : 0.f)) : -1e9f;
                    sacc[mi][ni][1] = v1ok ? (sacc[mi][ni][1] * ATT_SCALE + rpb_h[x01]
                                              + ((g0 != gm1) ? -100.f : 0.f)) : -1e9f;
                    sacc[mi][ni][2] = v0ok ? (sacc[mi][ni][2] * ATT_SCALE + rpb_h[x10]
                                              + ((g1 != gm0) ? -100.f : 0.f)) : -1e9f;
                    sacc[mi][ni][3] = v1ok ? (sacc[mi][ni][3] * ATT_SCALE + rpb_h[x11]
                                              + ((g1 != gm1) ? -100.f : 0.f)) : -1e9f;
                }
                float mx0 = -1e30f, mx1 = -1e30f;
                #pragma unroll
                for (int ni = 0; ni < 8; ni++) {
                    mx0 = fmaxf(mx0, fmaxf(sacc[mi][ni][0], sacc[mi][ni][1]));
                    mx1 = fmaxf(mx1, fmaxf(sacc[mi][ni][2], sacc[mi][ni][3]));
                }
                mx0 = fmaxf(mx0, __shfl_xor_sync(0xffffffffu, mx0, 1));
                mx0 = fmaxf(mx0, __shfl_xor_sync(0xffffffffu, mx0, 2));
                mx1 = fmaxf(mx1, __shfl_xor_sync(0xffffffffu, mx1, 1));
                mx1 = fmaxf(mx1, __shfl_xor_sync(0xffffffffu, mx1, 2));
                float s0 = 0.f, s1 = 0.f;
                #pragma unroll
                for (int ni = 0; ni < 8; ni++) {
                    float e0 = __expf(sacc[mi][ni][0] - mx0);
                    float e1 = __expf(sacc[mi][ni][1] - mx0);
                    float e2 = __expf(sacc[mi][ni][2] - mx1);
                    float e3 = __expf(sacc[mi][ni][3] - mx1);
                    sacc[mi][ni][0] = e0; sacc[mi][ni][1] = e1;
                    sacc[mi][ni][2] = e2; sacc[mi][ni][3] = e3;
                    s0 += e0 + e1; s1 += e2 + e3;
                }
                s0 += __shfl_xor_sync(0xffffffffu, s0, 1);
                s0 += __shfl_xor_sync(0xffffffffu, s0, 2);
                s1 += __shfl_xor_sync(0xffffffffu, s1, 1);
                s1 += __shfl_xor_sync(0xffffffffu, s1, 2);
                rinv[mi][0] = 1.0f / s0;
                rinv[mi][1] = 1.0f / s1;
            }

            float oacc[2][4][4];
            #pragma unroll
            for (int mi = 0; mi < 2; mi++)
                #pragma unroll
                for (int ni = 0; ni < 4; ni++) {
                    oacc[mi][ni][0] = 0.f; oacc[mi][ni][1] = 0.f;
                    oacc[mi][ni][2] = 0.f; oacc[mi][ni][3] = 0.f;
                }
            #pragma unroll
            for (int kbk = 0; kbk < 4; kbk++) {
                uint32_t vf[4][2];
                #pragma unroll
                for (int g = 0; g < 2; g++)
                    ldsm_x4_t(vf[2*g][0], vf[2*g][1], vf[2*g+1][0], vf[2*g+1][1],
                        vbb + (uint32_t)((kbk*16 + (sub&1)*8 + srow) * 80
                                         + ((sub>>1)*8 + g*16) * 2));
                #pragma unroll
                for (int mi = 0; mi < 2; mi++) {
                    uint32_t ap[4];
                    ap[0] = packh2(sacc[mi][2*kbk][0],   sacc[mi][2*kbk][1]);
                    ap[1] = packh2(sacc[mi][2*kbk][2],   sacc[mi][2*kbk][3]);
                    ap[2] = packh2(sacc[mi][2*kbk+1][0], sacc[mi][2*kbk+1][1]);
                    ap[3] = packh2(sacc[mi][2*kbk+1][2], sacc[mi][2*kbk+1][3]);
                    #pragma unroll
                    for (int ni = 0; ni < 4; ni++)
                        mma16816(oacc[mi][ni], ap, vf[ni]);
                }
            }

            #pragma unroll
            for (int mi = 0; mi < 2; mi++) {
                int r0 = rowb + mi * 16 + lr;
                int r1 = r0 + 8;
                float i0 = rinv[mi][0], i1 = rinv[mi][1];
                #pragma unroll
                for (int ni = 0; ni < 4; ni++) {
                    int col = ni * 8 + 2 * lc;
                    if (r0 < NTOK)
                        *(__half2*)(o + (size_t)(win * NTOK + r0) * CC + head * HD + col)
                            = __floats2half2_rn(oacc[mi][ni][0] * i0, oacc[mi][ni][1] * i0);
                    if (r1 < NTOK)
                        *(__half2*)(o + (size_t)(win * NTOK + r1) * CC + head * HD + col)
                            = __floats2half2_rn(oacc[mi][ni][2] * i1, oacc[mi][ni][3] * i1);
                }
            }
        }
        __syncwarp();
    }
}

// ---------------- host launcher ----------------
extern "C" void kernel_launch(void* const* d_in, const int* in_sizes, int n_in,
                              void* d_out, int out_size)
{
    const float* x      = (const float*)d_in[0];
    const float* ln1_s  = (const float*)d_in[1];
    const float* ln1_b  = (const float*)d_in[2];
    const float* qkv_w  = (const float*)d_in[3];
    const float* qkv_b  = (const float*)d_in[4];
    const float* rpb    = (const float*)d_in[5];
    const float* proj_w = (const float*)d_in[6];
    const float* proj_b = (const float*)d_in[7];
    const float* ln2_s  = (const float*)d_in[8];
    const float* ln2_b  = (const float*)d_in[9];
    const float* fc1_w  = (const float*)d_in[10];
    const float* fc1_b  = (const float*)d_in[11];
    const float* fc2_w  = (const float*)d_in[12];
    const float* fc2_b  = (const float*)d_in[13];
    float* out = (float*)d_out;

    __half *ph, *pqkv, *po, *pact, *pwt;
    cudaGetSymbolAddress((void**)&ph,   g_h16);
    cudaGetSymbolAddress((void**)&pqkv, g_qkv16);
    cudaGetSymbolAddress((void**)&po,   g_o16);
    cudaGetSymbolAddress((void**)&pact, g_act16);
    cudaGetSymbolAddress((void**)&pwt,  g_wt);

    static int smem_set = 0;
    if (!smem_set) {
        cudaFuncSetAttribute(hgemm_kernel<0, true >, cudaFuncAttributeMaxDynamicSharedMemorySize, HG_SMEM);
        cudaFuncSetAttribute(hgemm_kernel<1, true >, cudaFuncAttributeMaxDynamicSharedMemorySize, HG_SMEM);
        cudaFuncSetAttribute(hgemm_kernel<2, false>, cudaFuncAttributeMaxDynamicSharedMemorySize, HG_SMEM);
        cudaFuncSetAttribute(hgemm_kernel<3, false>, cudaFuncAttributeMaxDynamicSharedMemorySize, HG_SMEM);
        cudaFuncSetAttribute(attn_mma_kernel, cudaFuncAttributeMaxDynamicSharedMemorySize, ATT_SMEM);
        smem_set = 1;
    }

    // 0. weight convert + transpose (single launch, 4 segments)
    wconv_all_kernel<<<3072, dim3(32, 8)>>>(qkv_w, proj_w, fc1_w, fc2_w, pwt);

    // 1. LN1 + shift + window partition -> fp16
    ln_kernel<true><<<TOT/8, 256>>>(x, ln1_s, ln1_b, ph);
    // 2. QKV GEMM
    hgemm_kernel<0, true><<<dim3(1536/128, TOT/128), 256, HG_SMEM>>>(
        ph, pwt + WQKV_OFF, qkv_b, pqkv, nullptr, TOT, 1536, 512);
    // 3. tensor-core windowed attention
    attn_mma_kernel<<<BB * NWIN, 256, ATT_SMEM>>>(pqkv, rpb, po);
    // 4. proj GEMM + fused window-reverse scatter + residual -> f32 out
    hgemm_kernel<3, false><<<dim3(512/128, TOT/128), 256, HG_SMEM>>>(
        po, pwt + WPROJ_OFF, proj_b, out, x, TOT, 512, 512);
    // 5. LN2 -> fp16
    ln_kernel<false><<<TOT/8, 256>>>(out, ln2_s, ln2_b, ph);
    // 6. FC1 + GELU
    hgemm_kernel<1, true><<<dim3(HID/128, TOT/128), 256, HG_SMEM>>>(
        ph, pwt + WFC1_OFF, fc1_b, pact, nullptr, TOT, HID, 512);
    // 7. FC2 + residual
    hgemm_kernel<2, false><<<dim3(512/128, TOT/128), 256, HG_SMEM>>>(
        pact, pwt + WFC2_OFF, fc2_b, out, out, TOT, 512, HID);
}